// round 5
// baseline (speedup 1.0000x reference)
#include <cuda_runtime.h>
#include <math.h>
#include <stdint.h>

#define BATCH   2
#define S0      4095
#define SEQ     4096
#define DMODEL  512
#define NH      8
#define DH      64
#define DFF     2048
#define MROWS   (BATCH * S0)    // 8190
#define MPAD    (BATCH * SEQ)   // 8192
#define QKVN    1536

// ---------------- scratch ----------------
__device__ __align__(16) uint32_t g_xtf[(size_t)MPAD * DMODEL];
__device__ __align__(16) uint32_t g_Wqkv[(size_t)QKVN * DMODEL];
__device__ __align__(16) uint32_t g_W1t[(size_t)DFF * DMODEL];
__device__ __align__(16) uint32_t g_W2t[(size_t)DMODEL * DFF];
__device__ __align__(16) float    g_bqkv[QKVN];
__device__ __align__(16) float    g_qkv[(size_t)MPAD * QKVN];
__device__ __align__(16) float    g_attn[(size_t)MPAD * DMODEL];
__device__ __align__(16) float    g_hn[(size_t)MROWS * DMODEL];
__device__ __align__(16) uint32_t g_hntf[(size_t)MROWS * DMODEL];
__device__ __align__(16) uint32_t g_acttf[(size_t)MROWS * DFF];

__device__ __forceinline__ uint32_t f2tf(float x) {
    uint32_t r;
    asm("cvt.rna.tf32.f32 %0, %1;" : "=r"(r) : "f"(x));
    return r;
}
__device__ __forceinline__ float gelu_exact(float v) {
    return 0.5f * v * (1.0f + erff(v * 0.70710678118654752440f));
}
__device__ __forceinline__ void mma_tf32(float* c, const uint32_t* a,
                                         const uint32_t* b) {
    asm volatile(
        "mma.sync.aligned.m16n8k8.row.col.f32.tf32.tf32.f32 "
        "{%0,%1,%2,%3}, {%4,%5,%6,%7}, {%8,%9}, {%0,%1,%2,%3};"
        : "+f"(c[0]), "+f"(c[1]), "+f"(c[2]), "+f"(c[3])
        : "r"(a[0]), "r"(a[1]), "r"(a[2]), "r"(a[3]), "r"(b[0]), "r"(b[1]));
}

// ---------------------------------------------------------------------------
// tf32 mma.sync GEMM with fragment-packed SMEM.
// C[M,N] = A[M,K] @ B[N,K]^T ; 128x128 tile, BK=16, 256 thr (8 warps 4x2).
// SMEM holds tiles pre-shuffled into mma fragment order:
//   A word (m,k): addr = ((m>>4)*2 + (k>>3))*128 + ((m&7)<<4) + ((k&3)<<2)
//                        + ((k>>2)&1)*2 + ((m>>3)&1)
//   B word (n,k): addr = ((n>>4)*2 + (k>>3))*128 + ((n&7)<<4) + ((k&3)<<2)
//                        + ((n>>3)&1)*2 + ((k>>2)&1)
// so consumers fetch whole fragments with single LDS.128s.
// MODE 0: fp32 out = acc + bias
// MODE 1: tf32 out = f2tf(gelu(acc + bias))
// MODE 2: fp32 out = acc + bias + res
// ---------------------------------------------------------------------------
template<int MODE>
__global__ __launch_bounds__(256, 2)
void tfgemm(const uint32_t* __restrict__ A, const uint32_t* __restrict__ B,
            const float* __restrict__ bias, const float* __restrict__ res,
            float* __restrict__ outf, uint32_t* __restrict__ outtf,
            int M, int N, int K)
{
    __shared__ __align__(16) uint32_t Sf[3][4096];  // [buf][A 2048 | B 2048]

    const int tid = threadIdx.x, lane = tid & 31, wid = tid >> 5;
    const int wm = wid & 3, wn = wid >> 2;
    const int bn = blockIdx.x, bm = blockIdx.y;
    const int NT = K >> 4;

    // producer: thread stages row ar, k-cols [ac, ac+8)
    const int ar = tid >> 1;
    const int ac = (tid & 1) << 3;
    const int aGRow = bm * 128 + ar;
    const bool aValid = (aGRow < M);
    const uint32_t* aPtr = A + (size_t)(aValid ? aGRow : 0) * K + ac;
    const uint32_t* bPtr = B + (size_t)(bn * 128 + ar) * K + ac;

    const int abase = ((ar >> 4) * 2 + (ac >> 3)) * 128 + ((ar & 7) << 4)
                    + ((ar >> 3) & 1);
    const int bbase = ((ar >> 4) * 2 + (ac >> 3)) * 128 + ((ar & 7) << 4)
                    + (((ar >> 3) & 1) << 1);

    uint4 av0, av1, bv0, bv1;
    auto ldt = [&](int kt) {
        const uint4 z = make_uint4(0u, 0u, 0u, 0u);
        av0 = aValid ? *(const uint4*)(aPtr + kt * 16)     : z;
        av1 = aValid ? *(const uint4*)(aPtr + kt * 16 + 4) : z;
        bv0 = *(const uint4*)(bPtr + kt * 16);
        bv1 = *(const uint4*)(bPtr + kt * 16 + 4);
    };
    auto stt = [&](int buf) {
        uint32_t* Afb = &Sf[buf][0];
        uint32_t* Bfb = &Sf[buf][2048];
        uint32_t wa[8] = {av0.x, av0.y, av0.z, av0.w, av1.x, av1.y, av1.z, av1.w};
        uint32_t wb[8] = {bv0.x, bv0.y, bv0.z, bv0.w, bv1.x, bv1.y, bv1.z, bv1.w};
#pragma unroll
        for (int j = 0; j < 8; j++) {
            Afb[abase + ((j & 3) << 2) + ((j >> 2) << 1)] = wa[j];
            Bfb[bbase + ((j & 3) << 2) + (j >> 2)]        = wb[j];
        }
    };

    float acc[2][8][4];
#pragma unroll
    for (int i = 0; i < 2; i++)
#pragma unroll
        for (int j = 0; j < 8; j++)
#pragma unroll
            for (int q = 0; q < 4; q++) acc[i][j][q] = 0.0f;

    // prologue: tiles 0,1 to SMEM; tile 2 in regs
    ldt(0); stt(0);
    ldt(1); stt(1);
    if (NT > 2) ldt(2);
    __syncthreads();

    for (int kt = 0; kt < NT; kt++) {
        const uint32_t* Afb = &Sf[kt % 3][0];
        const uint32_t* Bfb = &Sf[kt % 3][2048];
#pragma unroll
        for (int ks = 0; ks < 2; ks++) {
            uint4 a[2], b[4];
#pragma unroll
            for (int mf = 0; mf < 2; mf++)
                a[mf] = *(const uint4*)&Afb[(((wm * 2 + mf) * 2 + ks) << 7) + (lane << 2)];
#pragma unroll
            for (int p = 0; p < 4; p++)
                b[p] = *(const uint4*)&Bfb[(((wn * 4 + p) * 2 + ks) << 7) + (lane << 2)];
#pragma unroll
            for (int mf = 0; mf < 2; mf++)
#pragma unroll
                for (int p = 0; p < 4; p++) {
                    mma_tf32(acc[mf][p * 2],     (const uint32_t*)&a[mf],
                             (const uint32_t*)&b[p]);
                    mma_tf32(acc[mf][p * 2 + 1], (const uint32_t*)&a[mf],
                             ((const uint32_t*)&b[p]) + 2);
                }
        }
        if (kt + 2 < NT) {
            stt((kt + 2) % 3);
            if (kt + 3 < NT) ldt(kt + 3);
        }
        __syncthreads();
    }

    // epilogue (m16n8k8 C frag: c0,c1 -> row r, c2,c3 -> row r+8; cols 2*(lane&3))
#pragma unroll
    for (int mf = 0; mf < 2; mf++) {
#pragma unroll
        for (int nf = 0; nf < 8; nf++) {
            const int r0  = bm * 128 + wm * 32 + mf * 16 + (lane >> 2);
            const int col = bn * 128 + wn * 64 + nf * 8 + (lane & 3) * 2;
            const float b0 = bias[col], b1 = bias[col + 1];
#pragma unroll
            for (int half = 0; half < 2; half++) {
                const int r = r0 + half * 8;
                if (r >= M) continue;
                float v0 = acc[mf][nf][half * 2 + 0] + b0;
                float v1 = acc[mf][nf][half * 2 + 1] + b1;
                if (MODE == 0) {
                    *(float2*)&outf[(size_t)r * N + col] = make_float2(v0, v1);
                } else if (MODE == 1) {
                    uint2 o = make_uint2(f2tf(gelu_exact(v0)), f2tf(gelu_exact(v1)));
                    *(uint2*)&outtf[(size_t)r * N + col] = o;
                } else {
                    const float* rr = res + (size_t)r * N + col;
                    *(float2*)&outf[(size_t)r * N + col] =
                        make_float2(v0 + rr[0], v1 + rr[1]);
                }
            }
        }
    }
}

// ---------------------------------------------------------------------------
// prep kernels (run before the first GEMM; ncu -s5 lands on launch 6 = GEMM)
// ---------------------------------------------------------------------------
__global__ void prep_x(const float* __restrict__ x, uint32_t* __restrict__ o)
{
    size_t idx = (size_t)blockIdx.x * blockDim.x + threadIdx.x;
    if (idx >= (size_t)MPAD * DMODEL) return;
    int r = (int)(idx >> 9), c = (int)(idx & 511);
    int s = r & (SEQ - 1), b = r >> 12;
    float v = (s < S0) ? x[((size_t)b * S0 + s) * DMODEL + c] : 0.f;
    o[idx] = f2tf(v);
}

__global__ void prep_wqkv(const float* __restrict__ Wq, const float* __restrict__ Wk,
                          const float* __restrict__ Wv, uint32_t* __restrict__ o)
{
    int idx = blockIdx.x * blockDim.x + threadIdx.x;   // n*512 + k
    if (idx >= QKVN * DMODEL) return;
    int k = idx & 511, n = idx >> 9;
    float v;
    if (n < 512)       v = Wq[(size_t)k * 512 + n] * 0.125f;
    else if (n < 1024) v = Wk[(size_t)k * 512 + (n - 512)];
    else               v = Wv[(size_t)k * 512 + (n - 1024)];
    o[idx] = f2tf(v);
}

__global__ void prep_wt(const float* __restrict__ W, uint32_t* __restrict__ o,
                        int N, int K)
{
    size_t idx = (size_t)blockIdx.x * blockDim.x + threadIdx.x;  // n*K + k
    if (idx >= (size_t)N * K) return;
    int n = (int)(idx / K), k = (int)(idx - (size_t)n * K);
    o[idx] = f2tf(W[(size_t)k * N + n]);
}

__global__ void prep_bias(const float* __restrict__ bq, const float* __restrict__ bk,
                          const float* __restrict__ bv, float* __restrict__ o)
{
    int n = blockIdx.x * blockDim.x + threadIdx.x;
    if (n >= QKVN) return;
    o[n] = (n < 512) ? bq[n] * 0.125f
         : (n < 1024) ? bk[n - 512] : bv[n - 1024];
}

// ---------------------------------------------------------------------------
// Sliding-window attention on fused qkv [row, 1536] (q pre-scaled).
// ---------------------------------------------------------------------------
__global__ __launch_bounds__(256)
void attn_kernel(const float* __restrict__ qkv, float* __restrict__ out)
{
    __shared__ float Ks[32 * DH];
    __shared__ float Vs[32 * DH];
    __shared__ float Ss[64 * 33];

    const int tid = threadIdx.x;
    const int q   = tid >> 2;
    const int dg  = tid & 3;
    const int h   = blockIdx.y;
    const int b   = blockIdx.z;
    const int t0  = blockIdx.x * 64;
    const int t   = t0 + q;

    const float* base = qkv + (size_t)b * SEQ * QKVN;
    const int qoff = h * DH;
    const int koff = 512 + h * DH;
    const int voff = 1024 + h * DH;

    float qr[16], o[16];
#pragma unroll
    for (int i = 0; i < 16; i += 4) {
        float4 v4 = *(const float4*)(base + (size_t)t * QKVN + qoff + dg * 16 + i);
        qr[i] = v4.x; qr[i+1] = v4.y; qr[i+2] = v4.z; qr[i+3] = v4.w;
        o[i] = 0.f; o[i+1] = 0.f; o[i+2] = 0.f; o[i+3] = 0.f;
    }
    float m = -1e30f, l = 0.0f;

    int s_lo = t0 - 128;       if (s_lo < 0) s_lo = 0;
    int s_hi = t0 + 63 + 128;  if (s_hi > S0 - 1) s_hi = S0 - 1;

    for (int sbk = s_lo; sbk <= s_hi; sbk += 32) {
        const int nk = min(32, s_hi - sbk + 1);
        __syncthreads();
#pragma unroll
        for (int rep = 0; rep < 2; rep++) {
            int ld  = tid + rep * 256;
            int row = ld >> 4;
            int cl  = (ld & 15) << 2;
            float4 kv, vv;
            if (row < nk) {
                kv = *(const float4*)(base + (size_t)(sbk + row) * QKVN + koff + cl);
                vv = *(const float4*)(base + (size_t)(sbk + row) * QKVN + voff + cl);
            } else {
                kv = make_float4(0.f, 0.f, 0.f, 0.f);
                vv = kv;
            }
            *(float4*)&Ks[row * DH + cl] = kv;
            *(float4*)&Vs[row * DH + cl] = vv;
        }
        __syncthreads();

        float part[32];
#pragma unroll
        for (int kk = 0; kk < 32; kk++) {
            const float* kr = &Ks[kk * DH + dg * 16];
            float sacc = 0.f;
#pragma unroll
            for (int i = 0; i < 16; i++) sacc = fmaf(qr[i], kr[i], sacc);
            part[kk] = sacc;
        }
        float tmax = -1e30f;
#pragma unroll
        for (int kk = 0; kk < 32; kk++) {
            float v = part[kk];
            v += __shfl_xor_sync(0xffffffffu, v, 1);
            v += __shfl_xor_sync(0xffffffffu, v, 2);
            int sg = sbk + kk;
            bool valid = (kk < nk) && (sg >= t - 128) && (sg <= t + 128);
            v = valid ? v : -1e30f;
            part[kk] = v;
            tmax = fmaxf(tmax, v);
        }
        float mn = fmaxf(m, tmax);
        float r  = __expf(m - mn);
        float lp = 0.f;
#pragma unroll
        for (int j = 0; j < 8; j++) {
            int kk = dg * 8 + j;
            float p = __expf(part[kk] - mn);
            lp += p;
            Ss[q * 33 + kk] = p;
        }
        lp += __shfl_xor_sync(0xffffffffu, lp, 1);
        lp += __shfl_xor_sync(0xffffffffu, lp, 2);
        l = l * r + lp;
        m = mn;
#pragma unroll
        for (int i = 0; i < 16; i++) o[i] *= r;
        __syncwarp();
#pragma unroll
        for (int kk = 0; kk < 32; kk++) {
            float p = Ss[q * 33 + kk];
            const float* vr = &Vs[kk * DH + dg * 16];
#pragma unroll
            for (int i = 0; i < 16; i++) o[i] = fmaf(p, vr[i], o[i]);
        }
    }

    {   // global key: row SEQ-1 (its k/v are the biases)
        const float* kg = base + (size_t)(SEQ - 1) * QKVN + koff + dg * 16;
        const float* vg = base + (size_t)(SEQ - 1) * QKVN + voff + dg * 16;
        float gs = 0.f;
#pragma unroll
        for (int i = 0; i < 16; i++) gs = fmaf(qr[i], kg[i], gs);
        gs += __shfl_xor_sync(0xffffffffu, gs, 1);
        gs += __shfl_xor_sync(0xffffffffu, gs, 2);
        float mn = fmaxf(m, gs);
        float r  = __expf(m - mn);
        float pg = __expf(gs - mn);
        l = l * r + pg;
#pragma unroll
        for (int i = 0; i < 16; i++) o[i] = o[i] * r + pg * vg[i];
    }

    if (t < S0) {
        float inv = 1.0f / l;
        float* op = out + ((size_t)b * SEQ + t) * DMODEL + h * DH + dg * 16;
#pragma unroll
        for (int i = 0; i < 16; i += 4)
            *(float4*)(op + i) = make_float4(o[i] * inv, o[i+1] * inv,
                                             o[i+2] * inv, o[i+3] * inv);
    }
}

// ---------------------------------------------------------------------------
// Residual + LayerNorm -> hn fp32 + hn tf32
// ---------------------------------------------------------------------------
__global__ __launch_bounds__(256)
void ln_kernel(const float* __restrict__ x, const float* __restrict__ attn,
               const float* __restrict__ gamma, const float* __restrict__ beta,
               float* __restrict__ hn, uint32_t* __restrict__ hntf)
{
    const int r = blockIdx.x;
    const int b = r / S0;
    const int s = r - b * S0;
    const float* xr = x + (size_t)r * DMODEL;
    const float* ar = attn + ((size_t)b * SEQ + s) * DMODEL;
    const int tid = threadIdx.x;

    float h0 = xr[tid]       + ar[tid];
    float h1 = xr[tid + 256] + ar[tid + 256];
    float sum = h0 + h1;
    float sq  = h0 * h0 + h1 * h1;
#pragma unroll
    for (int off = 16; off; off >>= 1) {
        sum += __shfl_xor_sync(0xffffffffu, sum, off);
        sq  += __shfl_xor_sync(0xffffffffu, sq,  off);
    }
    __shared__ float rs[8], rq[8];
    int w = tid >> 5, lane = tid & 31;
    if (lane == 0) { rs[w] = sum; rq[w] = sq; }
    __syncthreads();
    float ts = 0.f, tq = 0.f;
#pragma unroll
    for (int i = 0; i < 8; i++) { ts += rs[i]; tq += rq[i]; }
    float mu   = ts * (1.0f / DMODEL);
    float var  = tq * (1.0f / DMODEL) - mu * mu;
    float rstd = rsqrtf(var + 1e-5f);
    size_t base = (size_t)r * DMODEL;
    float v0 = (h0 - mu) * rstd * gamma[tid]       + beta[tid];
    float v1 = (h1 - mu) * rstd * gamma[tid + 256] + beta[tid + 256];
    hn[base + tid]         = v0;
    hn[base + tid + 256]   = v1;
    hntf[base + tid]       = f2tf(v0);
    hntf[base + tid + 256] = f2tf(v1);
}

// ---------------------------------------------------------------------------
extern "C" void kernel_launch(void* const* d_in, const int* in_sizes, int n_in,
                              void* d_out, int out_size)
{
    const float* x   = (const float*)d_in[0];
    const float* Wq  = (const float*)d_in[2];
    const float* bq  = (const float*)d_in[3];
    const float* Wk  = (const float*)d_in[4];
    const float* bk  = (const float*)d_in[5];
    const float* Wv  = (const float*)d_in[6];
    const float* bv  = (const float*)d_in[7];
    const float* lng = (const float*)d_in[14];
    const float* lnb = (const float*)d_in[15];
    const float* W1  = (const float*)d_in[16];
    const float* b1  = (const float*)d_in[17];
    const float* W2  = (const float*)d_in[18];
    const float* b2  = (const float*)d_in[19];

    uint32_t *pxtf, *pWqkv, *pW1t, *pW2t, *phntf, *pacttf;
    float *pbqkv, *pqkv, *pattn, *phn;
    cudaGetSymbolAddress((void**)&pxtf,   g_xtf);
    cudaGetSymbolAddress((void**)&pWqkv,  g_Wqkv);
    cudaGetSymbolAddress((void**)&pW1t,   g_W1t);
    cudaGetSymbolAddress((void**)&pW2t,   g_W2t);
    cudaGetSymbolAddress((void**)&pbqkv,  g_bqkv);
    cudaGetSymbolAddress((void**)&pqkv,   g_qkv);
    cudaGetSymbolAddress((void**)&pattn,  g_attn);
    cudaGetSymbolAddress((void**)&phn,    g_hn);
    cudaGetSymbolAddress((void**)&phntf,  g_hntf);
    cudaGetSymbolAddress((void**)&pacttf, g_acttf);

    dim3 blk(256);

    // launches 1..5: prep
    prep_x<<<(int)(((size_t)MPAD * DMODEL + 255) / 256), blk>>>(x, pxtf);
    prep_wqkv<<<(QKVN * DMODEL + 255) / 256, blk>>>(Wq, Wk, Wv, pWqkv);
    prep_wt<<<(int)(((size_t)DFF * DMODEL + 255) / 256), blk>>>(W1, pW1t, DFF, DMODEL);
    prep_wt<<<(int)(((size_t)DMODEL * DFF + 255) / 256), blk>>>(W2, pW2t, DMODEL, DFF);
    prep_bias<<<(QKVN + 255) / 256, blk>>>(bq, bk, bv, pbqkv);

    // launch 6: fused QKV GEMM [8192,1536] = x @ Wqkv^T  (ncu lands here)
    tfgemm<0><<<dim3(QKVN / 128, MPAD / 128), blk>>>(
        pxtf, pWqkv, pbqkv, nullptr, pqkv, nullptr, MPAD, QKVN, DMODEL);

    // 7: attention
    attn_kernel<<<dim3(SEQ / 64, NH, BATCH), blk>>>(pqkv, pattn);

    // 8: residual + LN
    ln_kernel<<<MROWS, blk>>>(x, pattn, lng, lnb, phn, phntf);

    // 9: FFN up + gelu -> act (tf32)
    tfgemm<1><<<dim3(DFF / 128, (MROWS + 127) / 128), blk>>>(
        phntf, pW1t, b1, nullptr, nullptr, pacttf, MROWS, DFF, DMODEL);

    // 10: FFN down + bias + residual -> out
    tfgemm<2><<<dim3(DMODEL / 128, (MROWS + 127) / 128), blk>>>(
        pacttf, pW2t, b2, phn, (float*)d_out, nullptr, MROWS, DMODEL, DFF);
}

// round 6
// speedup vs baseline: 1.4491x; 1.4491x over previous
#include <cuda_runtime.h>
#include <cuda_fp16.h>
#include <math.h>
#include <stdint.h>

#define BATCH   2
#define S0      4095
#define SEQ     4096
#define DMODEL  512
#define NH      8
#define DH      64
#define DFF     2048
#define MROWS   (BATCH * S0)    // 8190
#define MPAD    (BATCH * SEQ)   // 8192
#define QKVN    1536

// ---------------- scratch (packed fp16 pairs as uint32, k-major) ----------------
__device__ __align__(16) uint32_t g_xh[(size_t)MPAD * DMODEL / 2];
__device__ __align__(16) uint32_t g_Wqkv[(size_t)QKVN * DMODEL / 2];
__device__ __align__(16) uint32_t g_W1t[(size_t)DFF * DMODEL / 2];
__device__ __align__(16) uint32_t g_W2t[(size_t)DMODEL * DFF / 2];
__device__ __align__(16) float    g_bqkv[QKVN];
__device__ __align__(16) float    g_qkv[(size_t)MPAD * QKVN];
__device__ __align__(16) float    g_attn[(size_t)MPAD * DMODEL];
__device__ __align__(16) float    g_hn[(size_t)MROWS * DMODEL];
__device__ __align__(16) uint32_t g_hnh[(size_t)MROWS * DMODEL / 2];
__device__ __align__(16) uint32_t g_acth[(size_t)MROWS * DFF / 2];

__device__ __forceinline__ uint32_t f2h2(float a, float b) {
    __half2 h = __floats2half2_rn(a, b);
    return *(uint32_t*)&h;
}
__device__ __forceinline__ float gelu_exact(float v) {
    return 0.5f * v * (1.0f + erff(v * 0.70710678118654752440f));
}
__device__ __forceinline__ void mma_f16(float* c, const uint32_t* a,
                                        const uint32_t* b) {
    asm volatile(
        "mma.sync.aligned.m16n8k16.row.col.f32.f16.f16.f32 "
        "{%0,%1,%2,%3}, {%4,%5,%6,%7}, {%8,%9}, {%0,%1,%2,%3};"
        : "+f"(c[0]), "+f"(c[1]), "+f"(c[2]), "+f"(c[3])
        : "r"(a[0]), "r"(a[1]), "r"(a[2]), "r"(a[3]), "r"(b[0]), "r"(b[1]));
}

// ---------------------------------------------------------------------------
// fp16 mma.sync GEMM: C[M,N] = A[M,K] @ B[N,K]^T.
// A,B packed fp16 (uint32 = 2 k-values). 128x128 tile, BK=16 (8 words),
// 256 thr (8 warps 4x2), warp tile 32x64. SMEM [row][word] stride 12
// (conflict-free fragment loads; same scheme as the proven R2 kernel).
// MODE 0: fp32 = acc + bias   MODE 1: fp16x2 = gelu(acc+bias)
// MODE 2: fp32 = acc + bias + res
// ---------------------------------------------------------------------------
template<int MODE>
__global__ __launch_bounds__(256, 2)
void hgemm(const uint32_t* __restrict__ A, const uint32_t* __restrict__ B,
           const float* __restrict__ bias, const float* __restrict__ res,
           float* __restrict__ outf, uint32_t* __restrict__ outh,
           int M, int N, int K)
{
    __shared__ __align__(16) uint32_t As[128 * 12];
    __shared__ __align__(16) uint32_t Bs[128 * 12];

    const int tid  = threadIdx.x;
    const int lane = tid & 31;
    const int wid  = tid >> 5;
    const int wm   = wid & 3;
    const int wn   = wid >> 2;
    const int bn   = blockIdx.x;
    const int bm   = blockIdx.y;
    const int K2   = K >> 1;             // words per row

    // staging: thread -> row ar, word-cols [ac2, ac2+4)
    const int ar  = tid >> 1;
    const int ac2 = (tid & 1) << 2;
    const int aGRow = bm * 128 + ar;
    const bool aValid = (aGRow < M);
    const uint32_t* aPtr = A + (size_t)(aValid ? aGRow : 0) * K2 + ac2;
    const uint32_t* bPtr = B + (size_t)(bn * 128 + ar) * K2 + ac2;

    float acc[2][8][4];
#pragma unroll
    for (int i = 0; i < 2; i++)
#pragma unroll
        for (int j = 0; j < 8; j++)
#pragma unroll
            for (int q = 0; q < 4; q++) acc[i][j][q] = 0.0f;

    const uint4 z = make_uint4(0u, 0u, 0u, 0u);
    uint4 av = aValid ? *(const uint4*)aPtr : z;
    uint4 bv = *(const uint4*)bPtr;

    const int kk2 = lane & 3;
    const int rA  = wm * 32 + (lane >> 2);
    const int cB  = wn * 64 + (lane >> 2);

    for (int kt = 0; kt < K2; kt += 8) {
        __syncthreads();
        *(uint4*)&As[ar * 12 + ac2] = av;
        *(uint4*)&Bs[ar * 12 + ac2] = bv;
        __syncthreads();
        if (kt + 8 < K2) {
            av = aValid ? *(const uint4*)(aPtr + kt + 8) : z;
            bv = *(const uint4*)(bPtr + kt + 8);
        }

        uint32_t a[2][4];
#pragma unroll
        for (int mf = 0; mf < 2; mf++) {
            int rr = rA + mf * 16;
            a[mf][0] = As[rr * 12 + kk2];
            a[mf][1] = As[(rr + 8) * 12 + kk2];
            a[mf][2] = As[rr * 12 + kk2 + 4];
            a[mf][3] = As[(rr + 8) * 12 + kk2 + 4];
        }
        uint32_t b[8][2];
#pragma unroll
        for (int nf = 0; nf < 8; nf++) {
            b[nf][0] = Bs[(cB + nf * 8) * 12 + kk2];
            b[nf][1] = Bs[(cB + nf * 8) * 12 + kk2 + 4];
        }
#pragma unroll
        for (int mf = 0; mf < 2; mf++)
#pragma unroll
            for (int nf = 0; nf < 8; nf++)
                mma_f16(acc[mf][nf], a[mf], b[nf]);
    }

    // epilogue: c0,c1 -> row r, cols 2*(lane&3); c2,c3 -> row r+8
#pragma unroll
    for (int mf = 0; mf < 2; mf++) {
#pragma unroll
        for (int nf = 0; nf < 8; nf++) {
            const int r0  = bm * 128 + wm * 32 + mf * 16 + (lane >> 2);
            const int col = bn * 128 + wn * 64 + nf * 8 + (lane & 3) * 2;
            const float b0 = bias[col], b1 = bias[col + 1];
#pragma unroll
            for (int half = 0; half < 2; half++) {
                const int r = r0 + half * 8;
                if (r >= M) continue;
                float v0 = acc[mf][nf][half * 2 + 0] + b0;
                float v1 = acc[mf][nf][half * 2 + 1] + b1;
                if (MODE == 0) {
                    *(float2*)&outf[(size_t)r * N + col] = make_float2(v0, v1);
                } else if (MODE == 1) {
                    outh[(size_t)r * (N >> 1) + (col >> 1)] =
                        f2h2(gelu_exact(v0), gelu_exact(v1));
                } else {
                    const float* rr = res + (size_t)r * N + col;
                    *(float2*)&outf[(size_t)r * N + col] =
                        make_float2(v0 + rr[0], v1 + rr[1]);
                }
            }
        }
    }
}

// ---------------------------------------------------------------------------
// prep kernels
// ---------------------------------------------------------------------------
__global__ void prep_x(const float* __restrict__ x, uint32_t* __restrict__ o)
{
    size_t idx = (size_t)blockIdx.x * blockDim.x + threadIdx.x;  // word index
    if (idx >= (size_t)MPAD * DMODEL / 2) return;
    int r = (int)(idx >> 8), w = (int)(idx & 255);
    int s = r & (SEQ - 1), b = r >> 12;
    float v0 = 0.f, v1 = 0.f;
    if (s < S0) {
        const float* p = x + ((size_t)b * S0 + s) * DMODEL + 2 * w;
        v0 = p[0]; v1 = p[1];
    }
    o[idx] = f2h2(v0, v1);
}

__global__ void prep_wqkv(const float* __restrict__ Wq, const float* __restrict__ Wk,
                          const float* __restrict__ Wv, uint32_t* __restrict__ o)
{
    int idx = blockIdx.x * blockDim.x + threadIdx.x;     // n*256 + w
    if (idx >= QKVN * DMODEL / 2) return;
    int n = idx >> 8, w = idx & 255;
    int k0 = 2 * w;
    const float* W;
    float sc = 1.0f;
    int nn = n;
    if (n < 512)       { W = Wq; sc = 0.125f; }
    else if (n < 1024) { W = Wk; nn = n - 512; }
    else               { W = Wv; nn = n - 1024; }
    o[idx] = f2h2(W[(size_t)k0 * 512 + nn] * sc, W[(size_t)(k0 + 1) * 512 + nn] * sc);
}

__global__ void prep_wt(const float* __restrict__ W, uint32_t* __restrict__ o,
                        int N, int K)
{
    size_t idx = (size_t)blockIdx.x * blockDim.x + threadIdx.x;  // n*(K/2) + w
    if (idx >= (size_t)N * K / 2) return;
    int K2 = K >> 1;
    int n = (int)(idx / K2), w = (int)(idx - (size_t)n * K2);
    int k0 = 2 * w;
    o[idx] = f2h2(W[(size_t)k0 * N + n], W[(size_t)(k0 + 1) * N + n]);
}

__global__ void prep_bias(const float* __restrict__ bq, const float* __restrict__ bk,
                          const float* __restrict__ bv, float* __restrict__ o)
{
    int n = blockIdx.x * blockDim.x + threadIdx.x;
    if (n >= QKVN) return;
    o[n] = (n < 512) ? bq[n] * 0.125f
         : (n < 1024) ? bk[n - 512] : bv[n - 1024];
}

// ---------------------------------------------------------------------------
// Sliding-window attention on fused qkv [row, 1536] (q pre-scaled).
// ---------------------------------------------------------------------------
__global__ __launch_bounds__(256)
void attn_kernel(const float* __restrict__ qkv, float* __restrict__ out)
{
    __shared__ float Ks[32 * DH];
    __shared__ float Vs[32 * DH];
    __shared__ float Ss[64 * 33];

    const int tid = threadIdx.x;
    const int q   = tid >> 2;
    const int dg  = tid & 3;
    const int h   = blockIdx.y;
    const int b   = blockIdx.z;
    const int t0  = blockIdx.x * 64;
    const int t   = t0 + q;

    const float* base = qkv + (size_t)b * SEQ * QKVN;
    const int qoff = h * DH;
    const int koff = 512 + h * DH;
    const int voff = 1024 + h * DH;

    float qr[16], o[16];
#pragma unroll
    for (int i = 0; i < 16; i += 4) {
        float4 v4 = *(const float4*)(base + (size_t)t * QKVN + qoff + dg * 16 + i);
        qr[i] = v4.x; qr[i+1] = v4.y; qr[i+2] = v4.z; qr[i+3] = v4.w;
        o[i] = 0.f; o[i+1] = 0.f; o[i+2] = 0.f; o[i+3] = 0.f;
    }
    float m = -1e30f, l = 0.0f;

    int s_lo = t0 - 128;       if (s_lo < 0) s_lo = 0;
    int s_hi = t0 + 63 + 128;  if (s_hi > S0 - 1) s_hi = S0 - 1;

    for (int sbk = s_lo; sbk <= s_hi; sbk += 32) {
        const int nk = min(32, s_hi - sbk + 1);
        __syncthreads();
#pragma unroll
        for (int rep = 0; rep < 2; rep++) {
            int ld  = tid + rep * 256;
            int row = ld >> 4;
            int cl  = (ld & 15) << 2;
            float4 kv, vv;
            if (row < nk) {
                kv = *(const float4*)(base + (size_t)(sbk + row) * QKVN + koff + cl);
                vv = *(const float4*)(base + (size_t)(sbk + row) * QKVN + voff + cl);
            } else {
                kv = make_float4(0.f, 0.f, 0.f, 0.f);
                vv = kv;
            }
            *(float4*)&Ks[row * DH + cl] = kv;
            *(float4*)&Vs[row * DH + cl] = vv;
        }
        __syncthreads();

        float part[32];
#pragma unroll
        for (int kk = 0; kk < 32; kk++) {
            const float* kr = &Ks[kk * DH + dg * 16];
            float sacc = 0.f;
#pragma unroll
            for (int i = 0; i < 16; i++) sacc = fmaf(qr[i], kr[i], sacc);
            part[kk] = sacc;
        }
        float tmax = -1e30f;
#pragma unroll
        for (int kk = 0; kk < 32; kk++) {
            float v = part[kk];
            v += __shfl_xor_sync(0xffffffffu, v, 1);
            v += __shfl_xor_sync(0xffffffffu, v, 2);
            int sg = sbk + kk;
            bool valid = (kk < nk) && (sg >= t - 128) && (sg <= t + 128);
            v = valid ? v : -1e30f;
            part[kk] = v;
            tmax = fmaxf(tmax, v);
        }
        float mn = fmaxf(m, tmax);
        float r  = __expf(m - mn);
        float lp = 0.f;
#pragma unroll
        for (int j = 0; j < 8; j++) {
            int kk = dg * 8 + j;
            float p = __expf(part[kk] - mn);
            lp += p;
            Ss[q * 33 + kk] = p;
        }
        lp += __shfl_xor_sync(0xffffffffu, lp, 1);
        lp += __shfl_xor_sync(0xffffffffu, lp, 2);
        l = l * r + lp;
        m = mn;
#pragma unroll
        for (int i = 0; i < 16; i++) o[i] *= r;
        __syncwarp();
#pragma unroll
        for (int kk = 0; kk < 32; kk++) {
            float p = Ss[q * 33 + kk];
            const float* vr = &Vs[kk * DH + dg * 16];
#pragma unroll
            for (int i = 0; i < 16; i++) o[i] = fmaf(p, vr[i], o[i]);
        }
    }

    {   // global key (row SEQ-1: k/v are the biases)
        const float* kg = base + (size_t)(SEQ - 1) * QKVN + koff + dg * 16;
        const float* vg = base + (size_t)(SEQ - 1) * QKVN + voff + dg * 16;
        float gs = 0.f;
#pragma unroll
        for (int i = 0; i < 16; i++) gs = fmaf(qr[i], kg[i], gs);
        gs += __shfl_xor_sync(0xffffffffu, gs, 1);
        gs += __shfl_xor_sync(0xffffffffu, gs, 2);
        float mn = fmaxf(m, gs);
        float r  = __expf(m - mn);
        float pg = __expf(gs - mn);
        l = l * r + pg;
#pragma unroll
        for (int i = 0; i < 16; i++) o[i] = o[i] * r + pg * vg[i];
    }

    if (t < S0) {
        float inv = 1.0f / l;
        float* op = out + ((size_t)b * SEQ + t) * DMODEL + h * DH + dg * 16;
#pragma unroll
        for (int i = 0; i < 16; i += 4)
            *(float4*)(op + i) = make_float4(o[i] * inv, o[i+1] * inv,
                                             o[i+2] * inv, o[i+3] * inv);
    }
}

// ---------------------------------------------------------------------------
// Residual + LayerNorm -> hn fp32 + packed fp16
// Each thread: adjacent cols 2*tid, 2*tid+1.
// ---------------------------------------------------------------------------
__global__ __launch_bounds__(256)
void ln_kernel(const float* __restrict__ x, const float* __restrict__ attn,
               const float* __restrict__ gamma, const float* __restrict__ beta,
               float* __restrict__ hn, uint32_t* __restrict__ hnh)
{
    const int r = blockIdx.x;
    const int b = r / S0;
    const int s = r - b * S0;
    const int tid = threadIdx.x;
    const int c = tid * 2;

    float2 xv = *(const float2*)(x + (size_t)r * DMODEL + c);
    float2 av = *(const float2*)(attn + ((size_t)b * SEQ + s) * DMODEL + c);
    float h0 = xv.x + av.x;
    float h1 = xv.y + av.y;
    float sum = h0 + h1;
    float sq  = h0 * h0 + h1 * h1;
#pragma unroll
    for (int off = 16; off; off >>= 1) {
        sum += __shfl_xor_sync(0xffffffffu, sum, off);
        sq  += __shfl_xor_sync(0xffffffffu, sq,  off);
    }
    __shared__ float rs[8], rq[8];
    int w = tid >> 5, lane = tid & 31;
    if (lane == 0) { rs[w] = sum; rq[w] = sq; }
    __syncthreads();
    float ts = 0.f, tq = 0.f;
#pragma unroll
    for (int i = 0; i < 8; i++) { ts += rs[i]; tq += rq[i]; }
    float mu   = ts * (1.0f / DMODEL);
    float var  = tq * (1.0f / DMODEL) - mu * mu;
    float rstd = rsqrtf(var + 1e-5f);
    float v0 = (h0 - mu) * rstd * gamma[c]     + beta[c];
    float v1 = (h1 - mu) * rstd * gamma[c + 1] + beta[c + 1];
    size_t base = (size_t)r * DMODEL;
    *(float2*)(hn + base + c) = make_float2(v0, v1);
    hnh[(base >> 1) + tid] = f2h2(v0, v1);
}

// ---------------------------------------------------------------------------
extern "C" void kernel_launch(void* const* d_in, const int* in_sizes, int n_in,
                              void* d_out, int out_size)
{
    const float* x   = (const float*)d_in[0];
    const float* Wq  = (const float*)d_in[2];
    const float* bq  = (const float*)d_in[3];
    const float* Wk  = (const float*)d_in[4];
    const float* bk  = (const float*)d_in[5];
    const float* Wv  = (const float*)d_in[6];
    const float* bv  = (const float*)d_in[7];
    const float* lng = (const float*)d_in[14];
    const float* lnb = (const float*)d_in[15];
    const float* W1  = (const float*)d_in[16];
    const float* b1  = (const float*)d_in[17];
    const float* W2  = (const float*)d_in[18];
    const float* b2  = (const float*)d_in[19];

    uint32_t *pxh, *pWqkv, *pW1t, *pW2t, *phnh, *pacth;
    float *pbqkv, *pqkv, *pattn, *phn;
    cudaGetSymbolAddress((void**)&pxh,    g_xh);
    cudaGetSymbolAddress((void**)&pWqkv,  g_Wqkv);
    cudaGetSymbolAddress((void**)&pW1t,   g_W1t);
    cudaGetSymbolAddress((void**)&pW2t,   g_W2t);
    cudaGetSymbolAddress((void**)&pbqkv,  g_bqkv);
    cudaGetSymbolAddress((void**)&pqkv,   g_qkv);
    cudaGetSymbolAddress((void**)&pattn,  g_attn);
    cudaGetSymbolAddress((void**)&phn,    g_hn);
    cudaGetSymbolAddress((void**)&phnh,   g_hnh);
    cudaGetSymbolAddress((void**)&pacth,  g_acth);

    dim3 blk(256);

    // launches 1..5: prep  (ncu -s5 -> launch 6 = QKV GEMM)
    prep_x<<<(int)(((size_t)MPAD * DMODEL / 2 + 255) / 256), blk>>>(x, pxh);
    prep_wqkv<<<(QKVN * DMODEL / 2 + 255) / 256, blk>>>(Wq, Wk, Wv, pWqkv);
    prep_wt<<<(int)(((size_t)DFF * DMODEL / 2 + 255) / 256), blk>>>(W1, pW1t, DFF, DMODEL);
    prep_wt<<<(int)(((size_t)DMODEL * DFF / 2 + 255) / 256), blk>>>(W2, pW2t, DMODEL, DFF);
    prep_bias<<<(QKVN + 255) / 256, blk>>>(bq, bk, bv, pbqkv);

    // 6: fused QKV GEMM [8192,1536] = x @ Wqkv^T
    hgemm<0><<<dim3(QKVN / 128, MPAD / 128), blk>>>(
        pxh, pWqkv, pbqkv, nullptr, pqkv, nullptr, MPAD, QKVN, DMODEL);

    // 7: attention
    attn_kernel<<<dim3(SEQ / 64, NH, BATCH), blk>>>(pqkv, pattn);

    // 8: residual + LN
    ln_kernel<<<MROWS, blk>>>(x, pattn, lng, lnb, phn, phnh);

    // 9: FFN up + gelu -> act fp16
    hgemm<1><<<dim3(DFF / 128, (MROWS + 127) / 128), blk>>>(
        phnh, pW1t, b1, nullptr, nullptr, pacth, MROWS, DFF, DMODEL);

    // 10: FFN down + bias + residual -> out
    hgemm<2><<<dim3(DMODEL / 128, (MROWS + 127) / 128), blk>>>(
        pacth, pW2t, b2, phn, (float*)d_out, nullptr, MROWS, DMODEL, DFF);
}

// round 7
// speedup vs baseline: 1.4839x; 1.0240x over previous
#include <cuda_runtime.h>
#include <cuda_fp16.h>
#include <math.h>
#include <stdint.h>

#define BATCH   2
#define S0      4095
#define SEQ     4096
#define DMODEL  512
#define NH      8
#define DH      64
#define DFF     2048
#define MROWS   (BATCH * S0)    // 8190
#define MPAD    (BATCH * SEQ)   // 8192
#define QKVN    1536

// ---------------- scratch (packed fp16 pairs as uint32, k-major) ----------------
__device__ __align__(16) uint32_t g_xh[(size_t)MPAD * DMODEL / 2];
__device__ __align__(16) uint32_t g_Wqkv[(size_t)QKVN * DMODEL / 2];
__device__ __align__(16) uint32_t g_W1t[(size_t)DFF * DMODEL / 2];
__device__ __align__(16) uint32_t g_W2t[(size_t)DMODEL * DFF / 2];
__device__ __align__(16) float    g_bqkv[QKVN];
__device__ __align__(16) float    g_qkv[(size_t)MPAD * QKVN];
__device__ __align__(16) float    g_attn[(size_t)MPAD * DMODEL];
__device__ __align__(16) float    g_hn[(size_t)MROWS * DMODEL];
__device__ __align__(16) uint32_t g_hnh[(size_t)MROWS * DMODEL / 2];
__device__ __align__(16) uint32_t g_acth[(size_t)MROWS * DFF / 2];

__device__ __forceinline__ uint32_t smem_u32(const void* p) {
    uint32_t a;
    asm("{ .reg .u64 t; cvta.to.shared.u64 t, %1; cvt.u32.u64 %0, t; }"
        : "=r"(a) : "l"(p));
    return a;
}
__device__ __forceinline__ uint32_t f2h2(float a, float b) {
    __half2 h = __floats2half2_rn(a, b);
    return *(uint32_t*)&h;
}
__device__ __forceinline__ float gelu_exact(float v) {
    return 0.5f * v * (1.0f + erff(v * 0.70710678118654752440f));
}
__device__ __forceinline__ void mma_f16(float* c, const uint32_t* a,
                                        const uint32_t* b) {
    asm volatile(
        "mma.sync.aligned.m16n8k16.row.col.f32.f16.f16.f32 "
        "{%0,%1,%2,%3}, {%4,%5,%6,%7}, {%8,%9}, {%0,%1,%2,%3};"
        : "+f"(c[0]), "+f"(c[1]), "+f"(c[2]), "+f"(c[3])
        : "r"(a[0]), "r"(a[1]), "r"(a[2]), "r"(a[3]), "r"(b[0]), "r"(b[1]));
}
#define LDSM4(r0, r1, r2, r3, addr) \
    asm volatile("ldmatrix.sync.aligned.m8n8.x4.shared.b16 {%0,%1,%2,%3}, [%4];" \
        : "=r"(r0), "=r"(r1), "=r"(r2), "=r"(r3) : "r"(addr))

__device__ __forceinline__ void cpa16(uint32_t dst, const void* src, bool v) {
    int sz = v ? 16 : 0;
    asm volatile("cp.async.cg.shared.global [%0], [%1], 16, %2;"
        :: "r"(dst), "l"(src), "r"(sz) : "memory");
}

// ---------------------------------------------------------------------------
// fp16 GEMM v2: C[M,N] = A[M,K] @ B[N,K]^T.  Packed-fp16 operands (k-major).
// Block tile 128x256, 8 warps (2 m x 4 n), warp tile 64x64.
// BK = 32 halves (16 words). 3-stage cp.async pipeline, 1 sync/tile.
// SMEM rows stride 20 words -> LDSM phases conflict-free.
// Stage layout: A[128][20w] (2560w) then B[256][20w] (5120w) = 7680w/stage.
// MODE 0: fp32 = acc + bias   MODE 1: fp16x2 = gelu(acc+bias)
// MODE 2: fp32 = acc + bias + res
// ---------------------------------------------------------------------------
#define STGW 7680
#define GSMEM (3 * STGW * 4)   // 92160 bytes

template<int MODE>
__global__ __launch_bounds__(256, 1)
void hgemm2(const uint32_t* __restrict__ A, const uint32_t* __restrict__ B,
            const float* __restrict__ bias, const float* __restrict__ res,
            float* __restrict__ outf, uint32_t* __restrict__ outh,
            int M, int N, int K)
{
    extern __shared__ __align__(16) uint32_t S[];
    const uint32_t sm0 = smem_u32(S);
    const int tid  = threadIdx.x;
    const int lane = tid & 31;
    const int wid  = tid >> 5;
    const int wm   = wid & 1;       // 2 warp-rows x 64
    const int wn   = wid >> 1;      // 4 warp-cols x 64
    const int bn   = blockIdx.x;
    const int bm   = blockIdx.y;
    const int K2   = K >> 1;        // words per row
    const int NT   = K >> 5;        // BK=32 tiles

    // ldmatrix per-lane addressing
    const int aRow = wm * 64 + (lane & 15);
    const int aW   = (lane >> 4) << 2;
    const int bRow = wn * 64 + (lane & 7) + ((lane >> 4) << 3);
    const int bW   = ((lane >> 3) & 1) << 2;

    auto load_stage = [&](int kt, int st) {
        const uint32_t base = sm0 + st * (STGW * 4);
#pragma unroll
        for (int i = 0; i < 6; i++) {
            int c = i * 256 + tid;          // 1536 chunks of 16B
            bool isA = (c < 512);
            int idx  = isA ? c : c - 512;
            int row  = idx >> 2, w = idx & 3;
            int grow = isA ? (bm * 128 + row) : (bn * 256 + row);
            bool valid = (!isA) || (grow < M);
            const uint32_t* src = (isA ? A : B)
                + (size_t)(valid ? grow : 0) * K2 + kt * 16 + w * 4;
            uint32_t dst = base + ((isA ? 0 : 2560) + row * 20 + w * 4) * 4;
            cpa16(dst, src, valid);
        }
        asm volatile("cp.async.commit_group;" ::: "memory");
    };

    float acc[4][8][4];
#pragma unroll
    for (int i = 0; i < 4; i++)
#pragma unroll
        for (int j = 0; j < 8; j++)
#pragma unroll
            for (int q = 0; q < 4; q++) acc[i][j][q] = 0.0f;

    load_stage(0, 0);
    load_stage(1, 1);

    for (int kt = 0; kt < NT; kt++) {
        if (kt + 1 < NT) asm volatile("cp.async.wait_group 1;" ::: "memory");
        else             asm volatile("cp.async.wait_group 0;" ::: "memory");
        __syncthreads();
        if (kt + 2 < NT) load_stage(kt + 2, (kt + 2) % 3);

        const uint32_t sA = sm0 + (kt % 3) * (STGW * 4);
        const uint32_t sB = sA + 2560 * 4;
#pragma unroll
        for (int kh = 0; kh < 2; kh++) {
            uint32_t a[4][4], b[8][2];
#pragma unroll
            for (int mf = 0; mf < 4; mf++) {
                uint32_t ad = sA + (((aRow + mf * 16) * 20) + aW + kh * 8) * 4;
                LDSM4(a[mf][0], a[mf][1], a[mf][2], a[mf][3], ad);
            }
#pragma unroll
            for (int bp = 0; bp < 4; bp++) {
                uint32_t ad = sB + (((bRow + bp * 16) * 20) + bW + kh * 8) * 4;
                LDSM4(b[2 * bp][0], b[2 * bp][1],
                      b[2 * bp + 1][0], b[2 * bp + 1][1], ad);
            }
#pragma unroll
            for (int mf = 0; mf < 4; mf++)
#pragma unroll
                for (int nf = 0; nf < 8; nf++)
                    mma_f16(acc[mf][nf], a[mf], b[nf]);
        }
    }

    // epilogue
#pragma unroll
    for (int mf = 0; mf < 4; mf++) {
#pragma unroll
        for (int nf = 0; nf < 8; nf++) {
            const int r0  = bm * 128 + wm * 64 + mf * 16 + (lane >> 2);
            const int col = bn * 256 + wn * 64 + nf * 8 + (lane & 3) * 2;
            const float b0 = bias[col], b1 = bias[col + 1];
#pragma unroll
            for (int half = 0; half < 2; half++) {
                const int r = r0 + half * 8;
                if (r >= M) continue;
                float v0 = acc[mf][nf][half * 2 + 0] + b0;
                float v1 = acc[mf][nf][half * 2 + 1] + b1;
                if (MODE == 0) {
                    *(float2*)&outf[(size_t)r * N + col] = make_float2(v0, v1);
                } else if (MODE == 1) {
                    outh[(size_t)r * (N >> 1) + (col >> 1)] =
                        f2h2(gelu_exact(v0), gelu_exact(v1));
                } else {
                    const float* rr = res + (size_t)r * N + col;
                    *(float2*)&outf[(size_t)r * N + col] =
                        make_float2(v0 + rr[0], v1 + rr[1]);
                }
            }
        }
    }
}

// ---------------------------------------------------------------------------
// prep kernels
// ---------------------------------------------------------------------------
__global__ void prep_x(const float* __restrict__ x, uint32_t* __restrict__ o)
{
    size_t idx = (size_t)blockIdx.x * blockDim.x + threadIdx.x;
    if (idx >= (size_t)MPAD * DMODEL / 2) return;
    int r = (int)(idx >> 8), w = (int)(idx & 255);
    int s = r & (SEQ - 1), b = r >> 12;
    float v0 = 0.f, v1 = 0.f;
    if (s < S0) {
        const float* p = x + ((size_t)b * S0 + s) * DMODEL + 2 * w;
        v0 = p[0]; v1 = p[1];
    }
    o[idx] = f2h2(v0, v1);
}

__global__ void prep_wqkv(const float* __restrict__ Wq, const float* __restrict__ Wk,
                          const float* __restrict__ Wv, uint32_t* __restrict__ o)
{
    int idx = blockIdx.x * blockDim.x + threadIdx.x;     // n*256 + w
    if (idx >= QKVN * DMODEL / 2) return;
    int n = idx >> 8, w = idx & 255;
    int k0 = 2 * w;
    const float* W;
    float sc = 1.0f;
    int nn = n;
    if (n < 512)       { W = Wq; sc = 0.125f; }
    else if (n < 1024) { W = Wk; nn = n - 512; }
    else               { W = Wv; nn = n - 1024; }
    o[idx] = f2h2(W[(size_t)k0 * 512 + nn] * sc, W[(size_t)(k0 + 1) * 512 + nn] * sc);
}

__global__ void prep_wt(const float* __restrict__ W, uint32_t* __restrict__ o,
                        int N, int K)
{
    size_t idx = (size_t)blockIdx.x * blockDim.x + threadIdx.x;  // n*(K/2) + w
    if (idx >= (size_t)N * K / 2) return;
    int K2 = K >> 1;
    int n = (int)(idx / K2), w = (int)(idx - (size_t)n * K2);
    int k0 = 2 * w;
    o[idx] = f2h2(W[(size_t)k0 * N + n], W[(size_t)(k0 + 1) * N + n]);
}

__global__ void prep_bias(const float* __restrict__ bq, const float* __restrict__ bk,
                          const float* __restrict__ bv, float* __restrict__ o)
{
    int n = blockIdx.x * blockDim.x + threadIdx.x;
    if (n >= QKVN) return;
    o[n] = (n < 512) ? bq[n] * 0.125f
         : (n < 1024) ? bk[n - 512] : bv[n - 1024];
}

// ---------------------------------------------------------------------------
// Sliding-window attention on fused qkv [row, 1536] (q pre-scaled).
// ---------------------------------------------------------------------------
__global__ __launch_bounds__(256)
void attn_kernel(const float* __restrict__ qkv, float* __restrict__ out)
{
    __shared__ float Ks[32 * DH];
    __shared__ float Vs[32 * DH];
    __shared__ float Ss[64 * 33];

    const int tid = threadIdx.x;
    const int q   = tid >> 2;
    const int dg  = tid & 3;
    const int h   = blockIdx.y;
    const int b   = blockIdx.z;
    const int t0  = blockIdx.x * 64;
    const int t   = t0 + q;

    const float* base = qkv + (size_t)b * SEQ * QKVN;
    const int qoff = h * DH;
    const int koff = 512 + h * DH;
    const int voff = 1024 + h * DH;

    float qr[16], o[16];
#pragma unroll
    for (int i = 0; i < 16; i += 4) {
        float4 v4 = *(const float4*)(base + (size_t)t * QKVN + qoff + dg * 16 + i);
        qr[i] = v4.x; qr[i+1] = v4.y; qr[i+2] = v4.z; qr[i+3] = v4.w;
        o[i] = 0.f; o[i+1] = 0.f; o[i+2] = 0.f; o[i+3] = 0.f;
    }
    float m = -1e30f, l = 0.0f;

    int s_lo = t0 - 128;       if (s_lo < 0) s_lo = 0;
    int s_hi = t0 + 63 + 128;  if (s_hi > S0 - 1) s_hi = S0 - 1;

    for (int sbk = s_lo; sbk <= s_hi; sbk += 32) {
        const int nk = min(32, s_hi - sbk + 1);
        __syncthreads();
#pragma unroll
        for (int rep = 0; rep < 2; rep++) {
            int ld  = tid + rep * 256;
            int row = ld >> 4;
            int cl  = (ld & 15) << 2;
            float4 kv, vv;
            if (row < nk) {
                kv = *(const float4*)(base + (size_t)(sbk + row) * QKVN + koff + cl);
                vv = *(const float4*)(base + (size_t)(sbk + row) * QKVN + voff + cl);
            } else {
                kv = make_float4(0.f, 0.f, 0.f, 0.f);
                vv = kv;
            }
            *(float4*)&Ks[row * DH + cl] = kv;
            *(float4*)&Vs[row * DH + cl] = vv;
        }
        __syncthreads();

        float part[32];
#pragma unroll
        for (int kk = 0; kk < 32; kk++) {
            const float* kr = &Ks[kk * DH + dg * 16];
            float sacc = 0.f;
#pragma unroll
            for (int i = 0; i < 16; i++) sacc = fmaf(qr[i], kr[i], sacc);
            part[kk] = sacc;
        }
        float tmax = -1e30f;
#pragma unroll
        for (int kk = 0; kk < 32; kk++) {
            float v = part[kk];
            v += __shfl_xor_sync(0xffffffffu, v, 1);
            v += __shfl_xor_sync(0xffffffffu, v, 2);
            int sg = sbk + kk;
            bool valid = (kk < nk) && (sg >= t - 128) && (sg <= t + 128);
            v = valid ? v : -1e30f;
            part[kk] = v;
            tmax = fmaxf(tmax, v);
        }
        float mn = fmaxf(m, tmax);
        float r  = __expf(m - mn);
        float lp = 0.f;
#pragma unroll
        for (int j = 0; j < 8; j++) {
            int kk = dg * 8 + j;
            float p = __expf(part[kk] - mn);
            lp += p;
            Ss[q * 33 + kk] = p;
        }
        lp += __shfl_xor_sync(0xffffffffu, lp, 1);
        lp += __shfl_xor_sync(0xffffffffu, lp, 2);
        l = l * r + lp;
        m = mn;
#pragma unroll
        for (int i = 0; i < 16; i++) o[i] *= r;
        __syncwarp();
#pragma unroll
        for (int kk = 0; kk < 32; kk++) {
            float p = Ss[q * 33 + kk];
            const float* vr = &Vs[kk * DH + dg * 16];
#pragma unroll
            for (int i = 0; i < 16; i++) o[i] = fmaf(p, vr[i], o[i]);
        }
    }

    {   // global key (row SEQ-1: k/v are the biases)
        const float* kg = base + (size_t)(SEQ - 1) * QKVN + koff + dg * 16;
        const float* vg = base + (size_t)(SEQ - 1) * QKVN + voff + dg * 16;
        float gs = 0.f;
#pragma unroll
        for (int i = 0; i < 16; i++) gs = fmaf(qr[i], kg[i], gs);
        gs += __shfl_xor_sync(0xffffffffu, gs, 1);
        gs += __shfl_xor_sync(0xffffffffu, gs, 2);
        float mn = fmaxf(m, gs);
        float r  = __expf(m - mn);
        float pg = __expf(gs - mn);
        l = l * r + pg;
#pragma unroll
        for (int i = 0; i < 16; i++) o[i] = o[i] * r + pg * vg[i];
    }

    if (t < S0) {
        float inv = 1.0f / l;
        float* op = out + ((size_t)b * SEQ + t) * DMODEL + h * DH + dg * 16;
#pragma unroll
        for (int i = 0; i < 16; i += 4)
            *(float4*)(op + i) = make_float4(o[i] * inv, o[i+1] * inv,
                                             o[i+2] * inv, o[i+3] * inv);
    }
}

// ---------------------------------------------------------------------------
// Residual + LayerNorm -> hn fp32 + packed fp16
// ---------------------------------------------------------------------------
__global__ __launch_bounds__(256)
void ln_kernel(const float* __restrict__ x, const float* __restrict__ attn,
               const float* __restrict__ gamma, const float* __restrict__ beta,
               float* __restrict__ hn, uint32_t* __restrict__ hnh)
{
    const int r = blockIdx.x;
    const int b = r / S0;
    const int s = r - b * S0;
    const int tid = threadIdx.x;
    const int c = tid * 2;

    float2 xv = *(const float2*)(x + (size_t)r * DMODEL + c);
    float2 av = *(const float2*)(attn + ((size_t)b * SEQ + s) * DMODEL + c);
    float h0 = xv.x + av.x;
    float h1 = xv.y + av.y;
    float sum = h0 + h1;
    float sq  = h0 * h0 + h1 * h1;
#pragma unroll
    for (int off = 16; off; off >>= 1) {
        sum += __shfl_xor_sync(0xffffffffu, sum, off);
        sq  += __shfl_xor_sync(0xffffffffu, sq,  off);
    }
    __shared__ float rs[8], rq[8];
    int w = tid >> 5, lane = tid & 31;
    if (lane == 0) { rs[w] = sum; rq[w] = sq; }
    __syncthreads();
    float ts = 0.f, tq = 0.f;
#pragma unroll
    for (int i = 0; i < 8; i++) { ts += rs[i]; tq += rq[i]; }
    float mu   = ts * (1.0f / DMODEL);
    float var  = tq * (1.0f / DMODEL) - mu * mu;
    float rstd = rsqrtf(var + 1e-5f);
    float v0 = (h0 - mu) * rstd * gamma[c]     + beta[c];
    float v1 = (h1 - mu) * rstd * gamma[c + 1] + beta[c + 1];
    size_t base = (size_t)r * DMODEL;
    *(float2*)(hn + base + c) = make_float2(v0, v1);
    hnh[(base >> 1) + tid] = f2h2(v0, v1);
}

// ---------------------------------------------------------------------------
extern "C" void kernel_launch(void* const* d_in, const int* in_sizes, int n_in,
                              void* d_out, int out_size)
{
    const float* x   = (const float*)d_in[0];
    const float* Wq  = (const float*)d_in[2];
    const float* bq  = (const float*)d_in[3];
    const float* Wk  = (const float*)d_in[4];
    const float* bk  = (const float*)d_in[5];
    const float* Wv  = (const float*)d_in[6];
    const float* bv  = (const float*)d_in[7];
    const float* lng = (const float*)d_in[14];
    const float* lnb = (const float*)d_in[15];
    const float* W1  = (const float*)d_in[16];
    const float* b1  = (const float*)d_in[17];
    const float* W2  = (const float*)d_in[18];
    const float* b2  = (const float*)d_in[19];

    uint32_t *pxh, *pWqkv, *pW1t, *pW2t, *phnh, *pacth;
    float *pbqkv, *pqkv, *pattn, *phn;
    cudaGetSymbolAddress((void**)&pxh,    g_xh);
    cudaGetSymbolAddress((void**)&pWqkv,  g_Wqkv);
    cudaGetSymbolAddress((void**)&pW1t,   g_W1t);
    cudaGetSymbolAddress((void**)&pW2t,   g_W2t);
    cudaGetSymbolAddress((void**)&pbqkv,  g_bqkv);
    cudaGetSymbolAddress((void**)&pqkv,   g_qkv);
    cudaGetSymbolAddress((void**)&pattn,  g_attn);
    cudaGetSymbolAddress((void**)&phn,    g_hn);
    cudaGetSymbolAddress((void**)&phnh,   g_hnh);
    cudaGetSymbolAddress((void**)&pacth,  g_acth);

    cudaFuncSetAttribute(hgemm2<0>, cudaFuncAttributeMaxDynamicSharedMemorySize, GSMEM);
    cudaFuncSetAttribute(hgemm2<1>, cudaFuncAttributeMaxDynamicSharedMemorySize, GSMEM);
    cudaFuncSetAttribute(hgemm2<2>, cudaFuncAttributeMaxDynamicSharedMemorySize, GSMEM);

    dim3 blk(256);

    // launches 1..5: prep  (ncu -s5 -> launch 6 = QKV GEMM)
    prep_x<<<(int)(((size_t)MPAD * DMODEL / 2 + 255) / 256), blk>>>(x, pxh);
    prep_wqkv<<<(QKVN * DMODEL / 2 + 255) / 256, blk>>>(Wq, Wk, Wv, pWqkv);
    prep_wt<<<(int)(((size_t)DFF * DMODEL / 2 + 255) / 256), blk>>>(W1, pW1t, DFF, DMODEL);
    prep_wt<<<(int)(((size_t)DMODEL * DFF / 2 + 255) / 256), blk>>>(W2, pW2t, DMODEL, DFF);
    prep_bias<<<(QKVN + 255) / 256, blk>>>(bq, bk, bv, pbqkv);

    // 6: fused QKV GEMM [8192,1536] = x @ Wqkv^T
    hgemm2<0><<<dim3(QKVN / 256, MPAD / 128), blk, GSMEM>>>(
        pxh, pWqkv, pbqkv, nullptr, pqkv, nullptr, MPAD, QKVN, DMODEL);

    // 7: attention
    attn_kernel<<<dim3(SEQ / 64, NH, BATCH), blk>>>(pqkv, pattn);

    // 8: residual + LN
    ln_kernel<<<MROWS, blk>>>(x, pattn, lng, lnb, phn, phnh);

    // 9: FFN up + gelu -> act fp16
    hgemm2<1><<<dim3(DFF / 256, MPAD / 128), blk, GSMEM>>>(
        phnh, pW1t, b1, nullptr, nullptr, pacth, MROWS, DFF, DMODEL);

    // 10: FFN down + bias + residual -> out
    hgemm2<2><<<dim3(DMODEL / 256, MPAD / 128), blk, GSMEM>>>(
        pacth, pW2t, b2, phn, (float*)d_out, nullptr, MROWS, DMODEL, DFF);
}

// round 9
// speedup vs baseline: 4.1968x; 2.8282x over previous
#include <cuda_runtime.h>
#include <cuda_fp16.h>
#include <math.h>
#include <stdint.h>

#define BATCH   2
#define S0      4095
#define SEQ     4096
#define DMODEL  512
#define NH      8
#define DH      64
#define DFF     2048
#define MROWS   (BATCH * S0)    // 8190
#define MPAD    (BATCH * SEQ)   // 8192
#define QKVN    1536
#define QKVW    768             // words per qkv row

// ---------------- scratch ----------------
__device__ __align__(16) uint32_t g_xh[(size_t)MPAD * DMODEL / 2];
__device__ __align__(16) uint32_t g_Wqkv[(size_t)QKVN * DMODEL / 2];
__device__ __align__(16) uint32_t g_W1t[(size_t)DFF * DMODEL / 2];
__device__ __align__(16) uint32_t g_W2t[(size_t)DMODEL * DFF / 2];
__device__ __align__(16) float    g_bqkv[QKVN];
__device__ __align__(16) uint32_t g_qkvh[(size_t)MPAD * QKVW];   // packed fp16
__device__ __align__(16) float    g_attn[(size_t)MPAD * DMODEL];
__device__ __align__(16) float    g_hn[(size_t)MROWS * DMODEL];
__device__ __align__(16) uint32_t g_hnh[(size_t)MROWS * DMODEL / 2];
__device__ __align__(16) uint32_t g_acth[(size_t)MROWS * DFF / 2];

__device__ __forceinline__ uint32_t smem_u32(const void* p) {
    uint32_t a;
    asm("{ .reg .u64 t; cvta.to.shared.u64 t, %1; cvt.u32.u64 %0, t; }"
        : "=r"(a) : "l"(p));
    return a;
}
__device__ __forceinline__ uint32_t f2h2(float a, float b) {
    __half2 h = __floats2half2_rn(a, b);
    return *(uint32_t*)&h;
}
__device__ __forceinline__ float2 h22f2(uint32_t w) {
    __half2 h = *(__half2*)&w;
    return __half22float2(h);
}
__device__ __forceinline__ float gelu_exact(float v) {
    return 0.5f * v * (1.0f + erff(v * 0.70710678118654752440f));
}
__device__ __forceinline__ void mma_f16(float* c, const uint32_t* a,
                                        const uint32_t* b) {
    asm volatile(
        "mma.sync.aligned.m16n8k16.row.col.f32.f16.f16.f32 "
        "{%0,%1,%2,%3}, {%4,%5,%6,%7}, {%8,%9}, {%0,%1,%2,%3};"
        : "+f"(c[0]), "+f"(c[1]), "+f"(c[2]), "+f"(c[3])
        : "r"(a[0]), "r"(a[1]), "r"(a[2]), "r"(a[3]), "r"(b[0]), "r"(b[1]));
}
#define LDSM4(r0, r1, r2, r3, addr) \
    asm volatile("ldmatrix.sync.aligned.m8n8.x4.shared.b16 {%0,%1,%2,%3}, [%4];" \
        : "=r"(r0), "=r"(r1), "=r"(r2), "=r"(r3) : "r"(addr))

__device__ __forceinline__ void cpa16(uint32_t dst, const void* src, bool v) {
    int sz = v ? 16 : 0;
    asm volatile("cp.async.cg.shared.global [%0], [%1], 16, %2;"
        :: "r"(dst), "l"(src), "r"(sz) : "memory");
}

// ---------------------------------------------------------------------------
// fp16 GEMM: C[M,N] = A[M,K] @ B[N,K]^T. Block 128x256, warp tile 64x64,
// BK=32, 3-stage cp.async, stride-20-word SMEM, ldmatrix operands.
// MODE 0: fp16x2 = acc + bias     MODE 1: fp16x2 = gelu(acc + bias)
// MODE 2: fp32   = acc + bias + res
// ---------------------------------------------------------------------------
#define STGW 7680
#define GSMEM (3 * STGW * 4)

template<int MODE>
__global__ __launch_bounds__(256, 1)
void hgemm2(const uint32_t* __restrict__ A, const uint32_t* __restrict__ B,
            const float* __restrict__ bias, const float* __restrict__ res,
            float* __restrict__ outf, uint32_t* __restrict__ outh,
            int M, int N, int K)
{
    extern __shared__ __align__(16) uint32_t S[];
    const uint32_t sm0 = smem_u32(S);
    const int tid  = threadIdx.x;
    const int lane = tid & 31;
    const int wid  = tid >> 5;
    const int wm   = wid & 1;
    const int wn   = wid >> 1;
    const int bn   = blockIdx.x;
    const int bm   = blockIdx.y;
    const int K2   = K >> 1;
    const int NT   = K >> 5;

    const int aRow = wm * 64 + (lane & 15);
    const int aW   = (lane >> 4) << 2;
    const int bRow = wn * 64 + (lane & 7) + ((lane >> 4) << 3);
    const int bW   = ((lane >> 3) & 1) << 2;

    auto load_stage = [&](int kt, int st) {
        const uint32_t base = sm0 + st * (STGW * 4);
#pragma unroll
        for (int i = 0; i < 6; i++) {
            int c = i * 256 + tid;
            bool isA = (c < 512);
            int idx  = isA ? c : c - 512;
            int row  = idx >> 2, w = idx & 3;
            int grow = isA ? (bm * 128 + row) : (bn * 256 + row);
            bool valid = (!isA) || (grow < M);
            const uint32_t* src = (isA ? A : B)
                + (size_t)(valid ? grow : 0) * K2 + kt * 16 + w * 4;
            uint32_t dst = base + ((isA ? 0 : 2560) + row * 20 + w * 4) * 4;
            cpa16(dst, src, valid);
        }
        asm volatile("cp.async.commit_group;" ::: "memory");
    };

    float acc[4][8][4];
#pragma unroll
    for (int i = 0; i < 4; i++)
#pragma unroll
        for (int j = 0; j < 8; j++)
#pragma unroll
            for (int q = 0; q < 4; q++) acc[i][j][q] = 0.0f;

    load_stage(0, 0);
    load_stage(1, 1);

    for (int kt = 0; kt < NT; kt++) {
        if (kt + 1 < NT) asm volatile("cp.async.wait_group 1;" ::: "memory");
        else             asm volatile("cp.async.wait_group 0;" ::: "memory");
        __syncthreads();
        if (kt + 2 < NT) load_stage(kt + 2, (kt + 2) % 3);

        const uint32_t sA = sm0 + (kt % 3) * (STGW * 4);
        const uint32_t sB = sA + 2560 * 4;
#pragma unroll
        for (int kh = 0; kh < 2; kh++) {
            uint32_t a[4][4], b[8][2];
#pragma unroll
            for (int mf = 0; mf < 4; mf++) {
                uint32_t ad = sA + (((aRow + mf * 16) * 20) + aW + kh * 8) * 4;
                LDSM4(a[mf][0], a[mf][1], a[mf][2], a[mf][3], ad);
            }
#pragma unroll
            for (int bp = 0; bp < 4; bp++) {
                uint32_t ad = sB + (((bRow + bp * 16) * 20) + bW + kh * 8) * 4;
                LDSM4(b[2 * bp][0], b[2 * bp][1],
                      b[2 * bp + 1][0], b[2 * bp + 1][1], ad);
            }
#pragma unroll
            for (int mf = 0; mf < 4; mf++)
#pragma unroll
                for (int nf = 0; nf < 8; nf++)
                    mma_f16(acc[mf][nf], a[mf], b[nf]);
        }
    }

#pragma unroll
    for (int mf = 0; mf < 4; mf++) {
#pragma unroll
        for (int nf = 0; nf < 8; nf++) {
            const int r0  = bm * 128 + wm * 64 + mf * 16 + (lane >> 2);
            const int col = bn * 256 + wn * 64 + nf * 8 + (lane & 3) * 2;
            const float b0 = bias[col], b1 = bias[col + 1];
#pragma unroll
            for (int half = 0; half < 2; half++) {
                const int r = r0 + half * 8;
                if (r >= M) continue;
                float v0 = acc[mf][nf][half * 2 + 0] + b0;
                float v1 = acc[mf][nf][half * 2 + 1] + b1;
                if (MODE == 0) {
                    outh[(size_t)r * (N >> 1) + (col >> 1)] = f2h2(v0, v1);
                } else if (MODE == 1) {
                    outh[(size_t)r * (N >> 1) + (col >> 1)] =
                        f2h2(gelu_exact(v0), gelu_exact(v1));
                } else {
                    const float* rr = res + (size_t)r * N + col;
                    *(float2*)&outf[(size_t)r * N + col] =
                        make_float2(v0 + rr[0], v1 + rr[1]);
                }
            }
        }
    }
}

// ---------------------------------------------------------------------------
// prep kernels
// ---------------------------------------------------------------------------
__global__ void prep_x(const float* __restrict__ x, uint32_t* __restrict__ o)
{
    size_t idx = (size_t)blockIdx.x * blockDim.x + threadIdx.x;
    if (idx >= (size_t)MPAD * DMODEL / 2) return;
    int r = (int)(idx >> 8), w = (int)(idx & 255);
    int s = r & (SEQ - 1), b = r >> 12;
    float v0 = 0.f, v1 = 0.f;
    if (s < S0) {
        const float* p = x + ((size_t)b * S0 + s) * DMODEL + 2 * w;
        v0 = p[0]; v1 = p[1];
    }
    o[idx] = f2h2(v0, v1);
}

__global__ void prep_wqkv(const float* __restrict__ Wq, const float* __restrict__ Wk,
                          const float* __restrict__ Wv, uint32_t* __restrict__ o)
{
    int idx = blockIdx.x * blockDim.x + threadIdx.x;
    if (idx >= QKVN * DMODEL / 2) return;
    int n = idx >> 8, w = idx & 255;
    int k0 = 2 * w;
    const float* W;
    float sc = 1.0f;
    int nn = n;
    if (n < 512)       { W = Wq; sc = 0.125f; }
    else if (n < 1024) { W = Wk; nn = n - 512; }
    else               { W = Wv; nn = n - 1024; }
    o[idx] = f2h2(W[(size_t)k0 * 512 + nn] * sc, W[(size_t)(k0 + 1) * 512 + nn] * sc);
}

__global__ void prep_wt(const float* __restrict__ W, uint32_t* __restrict__ o,
                        int N, int K)
{
    size_t idx = (size_t)blockIdx.x * blockDim.x + threadIdx.x;
    if (idx >= (size_t)N * K / 2) return;
    int K2 = K >> 1;
    int n = (int)(idx / K2), w = (int)(idx - (size_t)n * K2);
    int k0 = 2 * w;
    o[idx] = f2h2(W[(size_t)k0 * N + n], W[(size_t)(k0 + 1) * N + n]);
}

__global__ void prep_bias(const float* __restrict__ bq, const float* __restrict__ bk,
                          const float* __restrict__ bv, float* __restrict__ o)
{
    int n = blockIdx.x * blockDim.x + threadIdx.x;
    if (n >= QKVN) return;
    o[n] = (n < 512) ? bq[n] * 0.125f
         : (n < 1024) ? bk[n - 512] : bv[n - 1024];
}

// ---------------------------------------------------------------------------
// Tensor-core sliding-window attention.
// Block = (b, h, 64-query tile), 128 threads (4 warps x 16 query rows).
// SMEM halves: Q[64][72] | K[320][72] | Vt[64][328] (V transposed).
// ldmatrix addressing here: lane bits 0-3 -> row, bit 4 -> k-offset, so the
// four 8x8 matrices are {rows0-7/off0, rows8-15/off0, rows0-7/off8,
// rows8-15/off8}; B-fragment pairs are therefore {r0,r2} and {r1,r3}.
// ---------------------------------------------------------------------------
#define AQ0 0
#define AK0 (64 * 72)                    // 4608
#define AV0 (AK0 + 320 * 72)             // 27648
#define ASMEMH (AV0 + 64 * 328)          // 48640 halves
#define ASMEM (ASMEMH * 2)               // 97280 bytes

__global__ __launch_bounds__(128, 1)
void attn_mma(const uint32_t* __restrict__ qkvh, float* __restrict__ out)
{
    extern __shared__ __align__(16) unsigned short SH[];
    const uint32_t sb = smem_u32(SH);
    const int tid  = threadIdx.x;
    const int lane = tid & 31;
    const int w    = tid >> 5;
    const int h    = blockIdx.y;
    const int b    = blockIdx.z;
    const int t0   = blockIdx.x * 64;
    const size_t rowbase = (size_t)b * SEQ;

    // ---- stage Q ----
#pragma unroll
    for (int i = 0; i < 4; i++) {
        int c = i * 128 + tid;
        int row = c >> 3, c16 = c & 7;
        const uint32_t* src = qkvh + (rowbase + t0 + row) * QKVW + h * 32 + c16 * 4;
        *(uint4*)&SH[AQ0 + row * 72 + c16 * 8] = *(const uint4*)src;
    }
    // ---- stage K (320 rows, clamped) ----
#pragma unroll
    for (int i = 0; i < 20; i++) {
        int c = i * 128 + tid;
        int row = c >> 3, c16 = c & 7;
        int key = t0 - 128 + row;
        key = key < 0 ? 0 : (key > SEQ - 1 ? SEQ - 1 : key);
        const uint32_t* src = qkvh + (rowbase + key) * QKVW + 256 + h * 32 + c16 * 4;
        *(uint4*)&SH[AK0 + row * 72 + c16 * 8] = *(const uint4*)src;
    }
    // ---- stage V transposed: Vt[d][keyidx] ----
#pragma unroll
    for (int i = 0; i < 20; i++) {
        int c = i * 128 + tid;
        int row = c >> 3, c16 = c & 7;
        int key = t0 - 128 + row;
        key = key < 0 ? 0 : (key > SEQ - 1 ? SEQ - 1 : key);
        const uint32_t* src = qkvh + (rowbase + key) * QKVW + 512 + h * 32 + c16 * 4;
        uint4 v = *(const uint4*)src;
        const unsigned short* hv = (const unsigned short*)&v;
#pragma unroll
        for (int j = 0; j < 8; j++)
            SH[AV0 + (c16 * 8 + j) * 328 + row] = hv[j];
    }
    __syncthreads();

    const int l15 = lane & 15;
    const int lh8 = (lane >> 4) << 3;
    const int kl0 = (lane & 3) << 1;
    const int r   = 16 * w + (lane >> 2);

    uint32_t aq[4][4];
#pragma unroll
    for (int j = 0; j < 4; j++) {
        uint32_t ad = sb + ((16 * w + l15) * 72 + 16 * j + lh8) * 2;
        LDSM4(aq[j][0], aq[j][1], aq[j][2], aq[j][3], ad);
    }

    float od[8][4];
#pragma unroll
    for (int nf = 0; nf < 8; nf++)
#pragma unroll
        for (int q = 0; q < 4; q++) od[nf][q] = 0.0f;
    float m0 = -1e30f, m1 = -1e30f, l0 = 0.f, l1 = 0.f;

    for (int c = 0; c < 5; c++) {
        const int ks = t0 - 128 + 64 * c;
        if (ks + 63 < 0 || ks > S0 - 1) continue;

        float sc[8][4];
#pragma unroll
        for (int nf = 0; nf < 8; nf++)
#pragma unroll
            for (int q = 0; q < 4; q++) sc[nf][q] = 0.0f;

        // S = Q @ K^T   (B pairs: {r0,r2} keys0-7, {r1,r3} keys8-15)
#pragma unroll
        for (int j = 0; j < 4; j++)
#pragma unroll
            for (int p = 0; p < 4; p++) {
                uint32_t r0, r1, r2, r3;
                uint32_t ad = sb + (AK0 + (c * 64 + 16 * p + l15) * 72
                                    + 16 * j + lh8) * 2;
                LDSM4(r0, r1, r2, r3, ad);
                uint32_t b0[2] = {r0, r2}, b1[2] = {r1, r3};
                mma_f16(sc[2 * p],     aq[j], b0);
                mma_f16(sc[2 * p + 1], aq[j], b1);
            }

        // mask + row max
        float mx0 = -1e30f, mx1 = -1e30f;
#pragma unroll
        for (int nf = 0; nf < 8; nf++) {
            int kl = 8 * nf + kl0;
            int u  = 64 * c + kl - r;
            int sg = ks + kl;
            bool k0ok = (sg >= 0) && (sg < S0);
            bool k1ok = (sg + 1 >= 0) && (sg + 1 < S0);
            bool v0 = k0ok && (u >= 0)     && (u <= 256);
            bool v1 = k1ok && (u + 1 >= 0) && (u + 1 <= 256);
            bool v2 = k0ok && (u - 8 >= 0) && (u - 8 <= 256);
            bool v3 = k1ok && (u - 7 >= 0) && (u - 7 <= 256);
            sc[nf][0] = v0 ? sc[nf][0] : -1e30f;
            sc[nf][1] = v1 ? sc[nf][1] : -1e30f;
            sc[nf][2] = v2 ? sc[nf][2] : -1e30f;
            sc[nf][3] = v3 ? sc[nf][3] : -1e30f;
            mx0 = fmaxf(mx0, fmaxf(sc[nf][0], sc[nf][1]));
            mx1 = fmaxf(mx1, fmaxf(sc[nf][2], sc[nf][3]));
        }
        mx0 = fmaxf(mx0, __shfl_xor_sync(0xffffffffu, mx0, 1));
        mx0 = fmaxf(mx0, __shfl_xor_sync(0xffffffffu, mx0, 2));
        mx1 = fmaxf(mx1, __shfl_xor_sync(0xffffffffu, mx1, 1));
        mx1 = fmaxf(mx1, __shfl_xor_sync(0xffffffffu, mx1, 2));

        float mn0 = fmaxf(m0, mx0), mn1 = fmaxf(m1, mx1);
        float s0 = __expf(m0 - mn0), s1 = __expf(m1 - mn1);
        float ls0 = 0.f, ls1 = 0.f;
        uint32_t pa[4][4];
#pragma unroll
        for (int nf = 0; nf < 8; nf++) {
            float e0 = __expf(sc[nf][0] - mn0);
            float e1 = __expf(sc[nf][1] - mn0);
            float e2 = __expf(sc[nf][2] - mn1);
            float e3 = __expf(sc[nf][3] - mn1);
            ls0 += e0 + e1; ls1 += e2 + e3;
            int j = nf >> 1, q = nf & 1;
            pa[j][2 * q]     = f2h2(e0, e1);
            pa[j][2 * q + 1] = f2h2(e2, e3);
        }
        ls0 += __shfl_xor_sync(0xffffffffu, ls0, 1);
        ls0 += __shfl_xor_sync(0xffffffffu, ls0, 2);
        ls1 += __shfl_xor_sync(0xffffffffu, ls1, 1);
        ls1 += __shfl_xor_sync(0xffffffffu, ls1, 2);
        l0 = l0 * s0 + ls0;
        l1 = l1 * s1 + ls1;
        m0 = mn0; m1 = mn1;
#pragma unroll
        for (int nf = 0; nf < 8; nf++) {
            od[nf][0] *= s0; od[nf][1] *= s0;
            od[nf][2] *= s1; od[nf][3] *= s1;
        }

        // O += P @ V   (B pairs: {r0,r2} d0-7, {r1,r3} d8-15)
#pragma unroll
        for (int j = 0; j < 4; j++)
#pragma unroll
            for (int p = 0; p < 4; p++) {
                uint32_t r0, r1, r2, r3;
                uint32_t ad = sb + (AV0 + (16 * p + l15) * 328
                                    + c * 64 + 16 * j + lh8) * 2;
                LDSM4(r0, r1, r2, r3, ad);
                uint32_t b0[2] = {r0, r2}, b1[2] = {r1, r3};
                mma_f16(od[2 * p],     pa[j], b0);
                mma_f16(od[2 * p + 1], pa[j], b1);
            }
    }

    // ---- global key (row SEQ-1; its k/v are the biases) ----
    {
        const uint32_t* kg = qkvh + (rowbase + SEQ - 1) * QKVW + 256 + h * 32
                           + (lane & 3) * 8;
        const uint32_t* q0 = (const uint32_t*)(SH + (size_t)(AQ0 + r * 72))
                           + (lane & 3) * 8;
        const uint32_t* q1 = (const uint32_t*)(SH + (size_t)(AQ0 + (r + 8) * 72))
                           + (lane & 3) * 8;
        float gs0 = 0.f, gs1 = 0.f;
#pragma unroll
        for (int i = 0; i < 8; i++) {
            float2 fk = h22f2(kg[i]);
            float2 f0 = h22f2(q0[i]);
            float2 f1 = h22f2(q1[i]);
            gs0 += f0.x * fk.x + f0.y * fk.y;
            gs1 += f1.x * fk.x + f1.y * fk.y;
        }
        gs0 += __shfl_xor_sync(0xffffffffu, gs0, 1);
        gs0 += __shfl_xor_sync(0xffffffffu, gs0, 2);
        gs1 += __shfl_xor_sync(0xffffffffu, gs1, 1);
        gs1 += __shfl_xor_sync(0xffffffffu, gs1, 2);

        float mn0 = fmaxf(m0, gs0), mn1 = fmaxf(m1, gs1);
        float s0 = __expf(m0 - mn0), s1 = __expf(m1 - mn1);
        float pg0 = __expf(gs0 - mn0), pg1 = __expf(gs1 - mn1);
        l0 = l0 * s0 + pg0;
        l1 = l1 * s1 + pg1;
        const uint32_t* vg = qkvh + (rowbase + SEQ - 1) * QKVW + 512 + h * 32
                           + (lane & 3);
#pragma unroll
        for (int nf = 0; nf < 8; nf++) {
            float2 fv = h22f2(vg[nf * 4]);
            od[nf][0] = od[nf][0] * s0 + pg0 * fv.x;
            od[nf][1] = od[nf][1] * s0 + pg0 * fv.y;
            od[nf][2] = od[nf][2] * s1 + pg1 * fv.x;
            od[nf][3] = od[nf][3] * s1 + pg1 * fv.y;
        }
    }

    // ---- write ----
    const float inv0 = 1.0f / l0, inv1 = 1.0f / l1;
    const int t = t0 + r;
    float* o0 = out + ((size_t)b * SEQ + t) * DMODEL + h * DH + kl0;
    float* o1 = o0 + 8 * (size_t)DMODEL;
#pragma unroll
    for (int nf = 0; nf < 8; nf++) {
        *(float2*)(o0 + nf * 8) = make_float2(od[nf][0] * inv0, od[nf][1] * inv0);
        *(float2*)(o1 + nf * 8) = make_float2(od[nf][2] * inv1, od[nf][3] * inv1);
    }
}

// ---------------------------------------------------------------------------
// Residual + LayerNorm -> hn fp32 + packed fp16
// ---------------------------------------------------------------------------
__global__ __launch_bounds__(256)
void ln_kernel(const float* __restrict__ x, const float* __restrict__ attn,
               const float* __restrict__ gamma, const float* __restrict__ beta,
               float* __restrict__ hn, uint32_t* __restrict__ hnh)
{
    const int r = blockIdx.x;
    const int b = r / S0;
    const int s = r - b * S0;
    const int tid = threadIdx.x;
    const int c = tid * 2;

    float2 xv = *(const float2*)(x + (size_t)r * DMODEL + c);
    float2 av = *(const float2*)(attn + ((size_t)b * SEQ + s) * DMODEL + c);
    float h0 = xv.x + av.x;
    float h1 = xv.y + av.y;
    float sum = h0 + h1;
    float sq  = h0 * h0 + h1 * h1;
#pragma unroll
    for (int off = 16; off; off >>= 1) {
        sum += __shfl_xor_sync(0xffffffffu, sum, off);
        sq  += __shfl_xor_sync(0xffffffffu, sq,  off);
    }
    __shared__ float rs[8], rq[8];
    int w = tid >> 5, lane = tid & 31;
    if (lane == 0) { rs[w] = sum; rq[w] = sq; }
    __syncthreads();
    float ts = 0.f, tq = 0.f;
#pragma unroll
    for (int i = 0; i < 8; i++) { ts += rs[i]; tq += rq[i]; }
    float mu   = ts * (1.0f / DMODEL);
    float var  = tq * (1.0f / DMODEL) - mu * mu;
    float rstd = rsqrtf(var + 1e-5f);
    float v0 = (h0 - mu) * rstd * gamma[c]     + beta[c];
    float v1 = (h1 - mu) * rstd * gamma[c + 1] + beta[c + 1];
    size_t base = (size_t)r * DMODEL;
    *(float2*)(hn + base + c) = make_float2(v0, v1);
    hnh[(base >> 1) + tid] = f2h2(v0, v1);
}

// ---------------------------------------------------------------------------
extern "C" void kernel_launch(void* const* d_in, const int* in_sizes, int n_in,
                              void* d_out, int out_size)
{
    const float* x   = (const float*)d_in[0];
    const float* Wq  = (const float*)d_in[2];
    const float* bq  = (const float*)d_in[3];
    const float* Wk  = (const float*)d_in[4];
    const float* bk  = (const float*)d_in[5];
    const float* Wv  = (const float*)d_in[6];
    const float* bv  = (const float*)d_in[7];
    const float* lng = (const float*)d_in[14];
    const float* lnb = (const float*)d_in[15];
    const float* W1  = (const float*)d_in[16];
    const float* b1  = (const float*)d_in[17];
    const float* W2  = (const float*)d_in[18];
    const float* b2  = (const float*)d_in[19];

    uint32_t *pxh, *pWqkv, *pW1t, *pW2t, *phnh, *pacth, *pqkvh;
    float *pbqkv, *pattn, *phn;
    cudaGetSymbolAddress((void**)&pxh,    g_xh);
    cudaGetSymbolAddress((void**)&pWqkv,  g_Wqkv);
    cudaGetSymbolAddress((void**)&pW1t,   g_W1t);
    cudaGetSymbolAddress((void**)&pW2t,   g_W2t);
    cudaGetSymbolAddress((void**)&pbqkv,  g_bqkv);
    cudaGetSymbolAddress((void**)&pqkvh,  g_qkvh);
    cudaGetSymbolAddress((void**)&pattn,  g_attn);
    cudaGetSymbolAddress((void**)&phn,    g_hn);
    cudaGetSymbolAddress((void**)&phnh,   g_hnh);
    cudaGetSymbolAddress((void**)&pacth,  g_acth);

    cudaFuncSetAttribute(hgemm2<0>, cudaFuncAttributeMaxDynamicSharedMemorySize, GSMEM);
    cudaFuncSetAttribute(hgemm2<1>, cudaFuncAttributeMaxDynamicSharedMemorySize, GSMEM);
    cudaFuncSetAttribute(hgemm2<2>, cudaFuncAttributeMaxDynamicSharedMemorySize, GSMEM);
    cudaFuncSetAttribute(attn_mma,  cudaFuncAttributeMaxDynamicSharedMemorySize, ASMEM);

    dim3 blk(256);

    prep_x<<<(int)(((size_t)MPAD * DMODEL / 2 + 255) / 256), blk>>>(x, pxh);
    prep_wqkv<<<(QKVN * DMODEL / 2 + 255) / 256, blk>>>(Wq, Wk, Wv, pWqkv);
    prep_wt<<<(int)(((size_t)DFF * DMODEL / 2 + 255) / 256), blk>>>(W1, pW1t, DFF, DMODEL);
    prep_wt<<<(int)(((size_t)DMODEL * DFF / 2 + 255) / 256), blk>>>(W2, pW2t, DMODEL, DFF);
    prep_bias<<<(QKVN + 255) / 256, blk>>>(bq, bk, bv, pbqkv);

    // fused QKV GEMM -> packed fp16 qkv
    hgemm2<0><<<dim3(QKVN / 256, MPAD / 128), blk, GSMEM>>>(
        pxh, pWqkv, pbqkv, nullptr, nullptr, pqkvh, MPAD, QKVN, DMODEL);

    // tensor-core attention
    attn_mma<<<dim3(SEQ / 64, NH, BATCH), dim3(128), ASMEM>>>(pqkvh, pattn);

    // residual + LN
    ln_kernel<<<MROWS, blk>>>(x, pattn, lng, lnb, phn, phnh);

    // FFN up + gelu -> fp16
    hgemm2<1><<<dim3(DFF / 256, MPAD / 128), blk, GSMEM>>>(
        phnh, pW1t, b1, nullptr, nullptr, pacth, MROWS, DFF, DMODEL);

    // FFN down + bias + residual -> out
    hgemm2<2><<<dim3(DMODEL / 256, MPAD / 128), blk, GSMEM>>>(
        pacth, pW2t, b2, phn, (float*)d_out, nullptr, MROWS, DMODEL, DFF);
}

// round 10
// speedup vs baseline: 4.3154x; 1.0283x over previous
#include <cuda_runtime.h>
#include <cuda_fp16.h>
#include <math.h>
#include <stdint.h>

#define BATCH   2
#define S0      4095
#define SEQ     4096
#define DMODEL  512
#define NH      8
#define DH      64
#define DFF     2048
#define MROWS   (BATCH * S0)    // 8190
#define MPAD    (BATCH * SEQ)   // 8192
#define QKVN    1536
#define QKVW    768             // words per qkv row

// ---------------- scratch ----------------
__device__ __align__(16) uint32_t g_xh[(size_t)MPAD * DMODEL / 2];
__device__ __align__(16) uint32_t g_Wqkv[(size_t)QKVN * DMODEL / 2];
__device__ __align__(16) uint32_t g_W1t[(size_t)DFF * DMODEL / 2];
__device__ __align__(16) uint32_t g_W2t[(size_t)DMODEL * DFF / 2];
__device__ __align__(16) float    g_bqkv[QKVN];
__device__ __align__(16) uint32_t g_qkvh[(size_t)MPAD * QKVW];   // packed fp16
__device__ __align__(16) float    g_attn[(size_t)MPAD * DMODEL];
__device__ __align__(16) float    g_hn[(size_t)MROWS * DMODEL];
__device__ __align__(16) uint32_t g_hnh[(size_t)MROWS * DMODEL / 2];
__device__ __align__(16) uint32_t g_acth[(size_t)MROWS * DFF / 2];

__device__ __forceinline__ uint32_t smem_u32(const void* p) {
    uint32_t a;
    asm("{ .reg .u64 t; cvta.to.shared.u64 t, %1; cvt.u32.u64 %0, t; }"
        : "=r"(a) : "l"(p));
    return a;
}
__device__ __forceinline__ uint32_t f2h2(float a, float b) {
    __half2 h = __floats2half2_rn(a, b);
    return *(uint32_t*)&h;
}
__device__ __forceinline__ float2 h22f2(uint32_t w) {
    __half2 h = *(__half2*)&w;
    return __half22float2(h);
}
__device__ __forceinline__ float gelu_exact(float v) {
    return 0.5f * v * (1.0f + erff(v * 0.70710678118654752440f));
}
__device__ __forceinline__ void mma_f16(float* c, const uint32_t* a,
                                        const uint32_t* b) {
    asm volatile(
        "mma.sync.aligned.m16n8k16.row.col.f32.f16.f16.f32 "
        "{%0,%1,%2,%3}, {%4,%5,%6,%7}, {%8,%9}, {%0,%1,%2,%3};"
        : "+f"(c[0]), "+f"(c[1]), "+f"(c[2]), "+f"(c[3])
        : "r"(a[0]), "r"(a[1]), "r"(a[2]), "r"(a[3]), "r"(b[0]), "r"(b[1]));
}
#define LDSM4(r0, r1, r2, r3, addr) \
    asm volatile("ldmatrix.sync.aligned.m8n8.x4.shared.b16 {%0,%1,%2,%3}, [%4];" \
        : "=r"(r0), "=r"(r1), "=r"(r2), "=r"(r3) : "r"(addr))

__device__ __forceinline__ void cpa16(uint32_t dst, const void* src, bool v) {
    int sz = v ? 16 : 0;
    asm volatile("cp.async.cg.shared.global [%0], [%1], 16, %2;"
        :: "r"(dst), "l"(src), "r"(sz) : "memory");
}

// ---------------------------------------------------------------------------
// fp16 GEMM: C[M,N] = A[M,K] @ B[N,K]^T. Block 128x256, warp tile 64x64,
// BK=32, 3-stage cp.async, stride-20-word SMEM, ldmatrix operands.
// MODE 0: fp16x2 = acc + bias     MODE 1: fp16x2 = gelu(acc + bias)
// MODE 2: fp32   = acc + bias + res
// ---------------------------------------------------------------------------
#define STGW 7680
#define GSMEM (3 * STGW * 4)

template<int MODE>
__global__ __launch_bounds__(256, 1)
void hgemm2(const uint32_t* __restrict__ A, const uint32_t* __restrict__ B,
            const float* __restrict__ bias, const float* __restrict__ res,
            float* __restrict__ outf, uint32_t* __restrict__ outh,
            int M, int N, int K)
{
    extern __shared__ __align__(16) uint32_t S[];
    const uint32_t sm0 = smem_u32(S);
    const int tid  = threadIdx.x;
    const int lane = tid & 31;
    const int wid  = tid >> 5;
    const int wm   = wid & 1;
    const int wn   = wid >> 1;
    const int bn   = blockIdx.x;
    const int bm   = blockIdx.y;
    const int K2   = K >> 1;
    const int NT   = K >> 5;

    const int aRow = wm * 64 + (lane & 15);
    const int aW   = (lane >> 4) << 2;
    const int bRow = wn * 64 + (lane & 7) + ((lane >> 4) << 3);
    const int bW   = ((lane >> 3) & 1) << 2;

    auto load_stage = [&](int kt, int st) {
        const uint32_t base = sm0 + st * (STGW * 4);
#pragma unroll
        for (int i = 0; i < 6; i++) {
            int c = i * 256 + tid;
            bool isA = (c < 512);
            int idx  = isA ? c : c - 512;
            int row  = idx >> 2, w = idx & 3;
            int grow = isA ? (bm * 128 + row) : (bn * 256 + row);
            bool valid = (!isA) || (grow < M);
            const uint32_t* src = (isA ? A : B)
                + (size_t)(valid ? grow : 0) * K2 + kt * 16 + w * 4;
            uint32_t dst = base + ((isA ? 0 : 2560) + row * 20 + w * 4) * 4;
            cpa16(dst, src, valid);
        }
        asm volatile("cp.async.commit_group;" ::: "memory");
    };

    float acc[4][8][4];
#pragma unroll
    for (int i = 0; i < 4; i++)
#pragma unroll
        for (int j = 0; j < 8; j++)
#pragma unroll
            for (int q = 0; q < 4; q++) acc[i][j][q] = 0.0f;

    load_stage(0, 0);
    load_stage(1, 1);

    for (int kt = 0; kt < NT; kt++) {
        if (kt + 1 < NT) asm volatile("cp.async.wait_group 1;" ::: "memory");
        else             asm volatile("cp.async.wait_group 0;" ::: "memory");
        __syncthreads();
        if (kt + 2 < NT) load_stage(kt + 2, (kt + 2) % 3);

        const uint32_t sA = sm0 + (kt % 3) * (STGW * 4);
        const uint32_t sB = sA + 2560 * 4;
#pragma unroll
        for (int kh = 0; kh < 2; kh++) {
            uint32_t a[4][4], b[8][2];
#pragma unroll
            for (int mf = 0; mf < 4; mf++) {
                uint32_t ad = sA + (((aRow + mf * 16) * 20) + aW + kh * 8) * 4;
                LDSM4(a[mf][0], a[mf][1], a[mf][2], a[mf][3], ad);
            }
#pragma unroll
            for (int bp = 0; bp < 4; bp++) {
                uint32_t ad = sB + (((bRow + bp * 16) * 20) + bW + kh * 8) * 4;
                LDSM4(b[2 * bp][0], b[2 * bp][1],
                      b[2 * bp + 1][0], b[2 * bp + 1][1], ad);
            }
#pragma unroll
            for (int mf = 0; mf < 4; mf++)
#pragma unroll
                for (int nf = 0; nf < 8; nf++)
                    mma_f16(acc[mf][nf], a[mf], b[nf]);
        }
    }

#pragma unroll
    for (int mf = 0; mf < 4; mf++) {
#pragma unroll
        for (int nf = 0; nf < 8; nf++) {
            const int r0  = bm * 128 + wm * 64 + mf * 16 + (lane >> 2);
            const int col = bn * 256 + wn * 64 + nf * 8 + (lane & 3) * 2;
            const float b0 = bias[col], b1 = bias[col + 1];
#pragma unroll
            for (int half = 0; half < 2; half++) {
                const int r = r0 + half * 8;
                if (r >= M) continue;
                float v0 = acc[mf][nf][half * 2 + 0] + b0;
                float v1 = acc[mf][nf][half * 2 + 1] + b1;
                if (MODE == 0) {
                    outh[(size_t)r * (N >> 1) + (col >> 1)] = f2h2(v0, v1);
                } else if (MODE == 1) {
                    outh[(size_t)r * (N >> 1) + (col >> 1)] =
                        f2h2(gelu_exact(v0), gelu_exact(v1));
                } else {
                    const float* rr = res + (size_t)r * N + col;
                    *(float2*)&outf[(size_t)r * N + col] =
                        make_float2(v0 + rr[0], v1 + rr[1]);
                }
            }
        }
    }
}

// ---------------------------------------------------------------------------
// prep kernels (coalesced transposes via SMEM tiles)
// ---------------------------------------------------------------------------
__global__ void prep_x(const float* __restrict__ x, uint32_t* __restrict__ o)
{
    size_t idx = (size_t)blockIdx.x * blockDim.x + threadIdx.x;
    if (idx >= (size_t)MPAD * DMODEL / 2) return;
    int r = (int)(idx >> 8), w = (int)(idx & 255);
    int s = r & (SEQ - 1), b = r >> 12;
    float v0 = 0.f, v1 = 0.f;
    if (s < S0) {
        const float* p = x + ((size_t)b * S0 + s) * DMODEL + 2 * w;
        v0 = p[0]; v1 = p[1];
    }
    o[idx] = f2h2(v0, v1);
}

// Transpose W[K][N] (row-major) tile -> out[n][k/2] packed fp16.
// Tile = 64 k x 32 n, 256 threads: both gmem read and write coalesced.
__device__ __forceinline__ void wt_tile(const float* __restrict__ W,
                                        uint32_t* __restrict__ o,
                                        int N, int dstStride, int dstRowOff,
                                        float scale, int k0, int n0)
{
    __shared__ float ts[64][33];
    const int tid = threadIdx.x;
#pragma unroll
    for (int i = 0; i < 8; i++) {
        int t = i * 256 + tid;
        int kr = t >> 5, nc = t & 31;
        ts[kr][nc] = W[(size_t)(k0 + kr) * N + n0 + nc];
    }
    __syncthreads();
#pragma unroll
    for (int i = 0; i < 4; i++) {
        int t = i * 256 + tid;
        int n = t >> 5, w = t & 31;
        o[(size_t)(dstRowOff + n0 + n) * dstStride + (k0 >> 1) + w] =
            f2h2(ts[2 * w][n] * scale, ts[2 * w + 1][n] * scale);
    }
}

__global__ __launch_bounds__(256)
void prep_wqkv_t(const float* __restrict__ Wq, const float* __restrict__ Wk,
                 const float* __restrict__ Wv, uint32_t* __restrict__ o)
{
    const int z = blockIdx.z;
    const float* W = (z == 0) ? Wq : (z == 1) ? Wk : Wv;
    float sc = (z == 0) ? 0.125f : 1.0f;
    wt_tile(W, o, DMODEL, 256, z * 512, sc, blockIdx.x * 64, blockIdx.y * 32);
}

__global__ __launch_bounds__(256)
void prep_wt2(const float* __restrict__ W, uint32_t* __restrict__ o,
              int N, int dstStride)
{
    wt_tile(W, o, N, dstStride, 0, 1.0f, blockIdx.x * 64, blockIdx.y * 32);
}

__global__ void prep_bias(const float* __restrict__ bq, const float* __restrict__ bk,
                          const float* __restrict__ bv, float* __restrict__ o)
{
    int n = blockIdx.x * blockDim.x + threadIdx.x;
    if (n >= QKVN) return;
    o[n] = (n < 512) ? bq[n] * 0.125f
         : (n < 1024) ? bk[n - 512] : bv[n - 1024];
}

// ---------------------------------------------------------------------------
// Tensor-core sliding-window attention (unchanged from R9 — proven).
// ---------------------------------------------------------------------------
#define AQ0 0
#define AK0 (64 * 72)
#define AV0 (AK0 + 320 * 72)
#define ASMEMH (AV0 + 64 * 328)
#define ASMEM (ASMEMH * 2)

__global__ __launch_bounds__(128, 1)
void attn_mma(const uint32_t* __restrict__ qkvh, float* __restrict__ out)
{
    extern __shared__ __align__(16) unsigned short SH[];
    const uint32_t sb = smem_u32(SH);
    const int tid  = threadIdx.x;
    const int lane = tid & 31;
    const int w    = tid >> 5;
    const int h    = blockIdx.y;
    const int b    = blockIdx.z;
    const int t0   = blockIdx.x * 64;
    const size_t rowbase = (size_t)b * SEQ;

#pragma unroll
    for (int i = 0; i < 4; i++) {
        int c = i * 128 + tid;
        int row = c >> 3, c16 = c & 7;
        const uint32_t* src = qkvh + (rowbase + t0 + row) * QKVW + h * 32 + c16 * 4;
        *(uint4*)&SH[AQ0 + row * 72 + c16 * 8] = *(const uint4*)src;
    }
#pragma unroll
    for (int i = 0; i < 20; i++) {
        int c = i * 128 + tid;
        int row = c >> 3, c16 = c & 7;
        int key = t0 - 128 + row;
        key = key < 0 ? 0 : (key > SEQ - 1 ? SEQ - 1 : key);
        const uint32_t* src = qkvh + (rowbase + key) * QKVW + 256 + h * 32 + c16 * 4;
        *(uint4*)&SH[AK0 + row * 72 + c16 * 8] = *(const uint4*)src;
    }
#pragma unroll
    for (int i = 0; i < 20; i++) {
        int c = i * 128 + tid;
        int row = c >> 3, c16 = c & 7;
        int key = t0 - 128 + row;
        key = key < 0 ? 0 : (key > SEQ - 1 ? SEQ - 1 : key);
        const uint32_t* src = qkvh + (rowbase + key) * QKVW + 512 + h * 32 + c16 * 4;
        uint4 v = *(const uint4*)src;
        const unsigned short* hv = (const unsigned short*)&v;
#pragma unroll
        for (int j = 0; j < 8; j++)
            SH[AV0 + (c16 * 8 + j) * 328 + row] = hv[j];
    }
    __syncthreads();

    const int l15 = lane & 15;
    const int lh8 = (lane >> 4) << 3;
    const int kl0 = (lane & 3) << 1;
    const int r   = 16 * w + (lane >> 2);

    uint32_t aq[4][4];
#pragma unroll
    for (int j = 0; j < 4; j++) {
        uint32_t ad = sb + ((16 * w + l15) * 72 + 16 * j + lh8) * 2;
        LDSM4(aq[j][0], aq[j][1], aq[j][2], aq[j][3], ad);
    }

    float od[8][4];
#pragma unroll
    for (int nf = 0; nf < 8; nf++)
#pragma unroll
        for (int q = 0; q < 4; q++) od[nf][q] = 0.0f;
    float m0 = -1e30f, m1 = -1e30f, l0 = 0.f, l1 = 0.f;

    for (int c = 0; c < 5; c++) {
        const int ks = t0 - 128 + 64 * c;
        if (ks + 63 < 0 || ks > S0 - 1) continue;

        float sc[8][4];
#pragma unroll
        for (int nf = 0; nf < 8; nf++)
#pragma unroll
            for (int q = 0; q < 4; q++) sc[nf][q] = 0.0f;

#pragma unroll
        for (int j = 0; j < 4; j++)
#pragma unroll
            for (int p = 0; p < 4; p++) {
                uint32_t r0, r1, r2, r3;
                uint32_t ad = sb + (AK0 + (c * 64 + 16 * p + l15) * 72
                                    + 16 * j + lh8) * 2;
                LDSM4(r0, r1, r2, r3, ad);
                uint32_t b0[2] = {r0, r2}, b1[2] = {r1, r3};
                mma_f16(sc[2 * p],     aq[j], b0);
                mma_f16(sc[2 * p + 1], aq[j], b1);
            }

        float mx0 = -1e30f, mx1 = -1e30f;
#pragma unroll
        for (int nf = 0; nf < 8; nf++) {
            int kl = 8 * nf + kl0;
            int u  = 64 * c + kl - r;
            int sg = ks + kl;
            bool k0ok = (sg >= 0) && (sg < S0);
            bool k1ok = (sg + 1 >= 0) && (sg + 1 < S0);
            bool v0 = k0ok && (u >= 0)     && (u <= 256);
            bool v1 = k1ok && (u + 1 >= 0) && (u + 1 <= 256);
            bool v2 = k0ok && (u - 8 >= 0) && (u - 8 <= 256);
            bool v3 = k1ok && (u - 7 >= 0) && (u - 7 <= 256);
            sc[nf][0] = v0 ? sc[nf][0] : -1e30f;
            sc[nf][1] = v1 ? sc[nf][1] : -1e30f;
            sc[nf][2] = v2 ? sc[nf][2] : -1e30f;
            sc[nf][3] = v3 ? sc[nf][3] : -1e30f;
            mx0 = fmaxf(mx0, fmaxf(sc[nf][0], sc[nf][1]));
            mx1 = fmaxf(mx1, fmaxf(sc[nf][2], sc[nf][3]));
        }
        mx0 = fmaxf(mx0, __shfl_xor_sync(0xffffffffu, mx0, 1));
        mx0 = fmaxf(mx0, __shfl_xor_sync(0xffffffffu, mx0, 2));
        mx1 = fmaxf(mx1, __shfl_xor_sync(0xffffffffu, mx1, 1));
        mx1 = fmaxf(mx1, __shfl_xor_sync(0xffffffffu, mx1, 2));

        float mn0 = fmaxf(m0, mx0), mn1 = fmaxf(m1, mx1);
        float s0 = __expf(m0 - mn0), s1 = __expf(m1 - mn1);
        float ls0 = 0.f, ls1 = 0.f;
        uint32_t pa[4][4];
#pragma unroll
        for (int nf = 0; nf < 8; nf++) {
            float e0 = __expf(sc[nf][0] - mn0);
            float e1 = __expf(sc[nf][1] - mn0);
            float e2 = __expf(sc[nf][2] - mn1);
            float e3 = __expf(sc[nf][3] - mn1);
            ls0 += e0 + e1; ls1 += e2 + e3;
            int j = nf >> 1, q = nf & 1;
            pa[j][2 * q]     = f2h2(e0, e1);
            pa[j][2 * q + 1] = f2h2(e2, e3);
        }
        ls0 += __shfl_xor_sync(0xffffffffu, ls0, 1);
        ls0 += __shfl_xor_sync(0xffffffffu, ls0, 2);
        ls1 += __shfl_xor_sync(0xffffffffu, ls1, 1);
        ls1 += __shfl_xor_sync(0xffffffffu, ls1, 2);
        l0 = l0 * s0 + ls0;
        l1 = l1 * s1 + ls1;
        m0 = mn0; m1 = mn1;
#pragma unroll
        for (int nf = 0; nf < 8; nf++) {
            od[nf][0] *= s0; od[nf][1] *= s0;
            od[nf][2] *= s1; od[nf][3] *= s1;
        }

#pragma unroll
        for (int j = 0; j < 4; j++)
#pragma unroll
            for (int p = 0; p < 4; p++) {
                uint32_t r0, r1, r2, r3;
                uint32_t ad = sb + (AV0 + (16 * p + l15) * 328
                                    + c * 64 + 16 * j + lh8) * 2;
                LDSM4(r0, r1, r2, r3, ad);
                uint32_t b0[2] = {r0, r2}, b1[2] = {r1, r3};
                mma_f16(od[2 * p],     pa[j], b0);
                mma_f16(od[2 * p + 1], pa[j], b1);
            }
    }

    {
        const uint32_t* kg = qkvh + (rowbase + SEQ - 1) * QKVW + 256 + h * 32
                           + (lane & 3) * 8;
        const uint32_t* q0 = (const uint32_t*)(SH + (size_t)(AQ0 + r * 72))
                           + (lane & 3) * 8;
        const uint32_t* q1 = (const uint32_t*)(SH + (size_t)(AQ0 + (r + 8) * 72))
                           + (lane & 3) * 8;
        float gs0 = 0.f, gs1 = 0.f;
#pragma unroll
        for (int i = 0; i < 8; i++) {
            float2 fk = h22f2(kg[i]);
            float2 f0 = h22f2(q0[i]);
            float2 f1 = h22f2(q1[i]);
            gs0 += f0.x * fk.x + f0.y * fk.y;
            gs1 += f1.x * fk.x + f1.y * fk.y;
        }
        gs0 += __shfl_xor_sync(0xffffffffu, gs0, 1);
        gs0 += __shfl_xor_sync(0xffffffffu, gs0, 2);
        gs1 += __shfl_xor_sync(0xffffffffu, gs1, 1);
        gs1 += __shfl_xor_sync(0xffffffffu, gs1, 2);

        float mn0 = fmaxf(m0, gs0), mn1 = fmaxf(m1, gs1);
        float s0 = __expf(m0 - mn0), s1 = __expf(m1 - mn1);
        float pg0 = __expf(gs0 - mn0), pg1 = __expf(gs1 - mn1);
        l0 = l0 * s0 + pg0;
        l1 = l1 * s1 + pg1;
        const uint32_t* vg = qkvh + (rowbase + SEQ - 1) * QKVW + 512 + h * 32
                           + (lane & 3);
#pragma unroll
        for (int nf = 0; nf < 8; nf++) {
            float2 fv = h22f2(vg[nf * 4]);
            od[nf][0] = od[nf][0] * s0 + pg0 * fv.x;
            od[nf][1] = od[nf][1] * s0 + pg0 * fv.y;
            od[nf][2] = od[nf][2] * s1 + pg1 * fv.x;
            od[nf][3] = od[nf][3] * s1 + pg1 * fv.y;
        }
    }

    const float inv0 = 1.0f / l0, inv1 = 1.0f / l1;
    const int t = t0 + r;
    float* o0 = out + ((size_t)b * SEQ + t) * DMODEL + h * DH + kl0;
    float* o1 = o0 + 8 * (size_t)DMODEL;
#pragma unroll
    for (int nf = 0; nf < 8; nf++) {
        *(float2*)(o0 + nf * 8) = make_float2(od[nf][0] * inv0, od[nf][1] * inv0);
        *(float2*)(o1 + nf * 8) = make_float2(od[nf][2] * inv1, od[nf][3] * inv1);
    }
}

// ---------------------------------------------------------------------------
// Residual + LayerNorm -> hn fp32 + packed fp16
// ---------------------------------------------------------------------------
__global__ __launch_bounds__(256)
void ln_kernel(const float* __restrict__ x, const float* __restrict__ attn,
               const float* __restrict__ gamma, const float* __restrict__ beta,
               float* __restrict__ hn, uint32_t* __restrict__ hnh)
{
    const int r = blockIdx.x;
    const int b = r / S0;
    const int s = r - b * S0;
    const int tid = threadIdx.x;
    const int c = tid * 2;

    float2 xv = *(const float2*)(x + (size_t)r * DMODEL + c);
    float2 av = *(const float2*)(attn + ((size_t)b * SEQ + s) * DMODEL + c);
    float h0 = xv.x + av.x;
    float h1 = xv.y + av.y;
    float sum = h0 + h1;
    float sq  = h0 * h0 + h1 * h1;
#pragma unroll
    for (int off = 16; off; off >>= 1) {
        sum += __shfl_xor_sync(0xffffffffu, sum, off);
        sq  += __shfl_xor_sync(0xffffffffu, sq,  off);
    }
    __shared__ float rs[8], rq[8];
    int w = tid >> 5, lane = tid & 31;
    if (lane == 0) { rs[w] = sum; rq[w] = sq; }
    __syncthreads();
    float ts = 0.f, tq = 0.f;
#pragma unroll
    for (int i = 0; i < 8; i++) { ts += rs[i]; tq += rq[i]; }
    float mu   = ts * (1.0f / DMODEL);
    float var  = tq * (1.0f / DMODEL) - mu * mu;
    float rstd = rsqrtf(var + 1e-5f);
    float v0 = (h0 - mu) * rstd * gamma[c]     + beta[c];
    float v1 = (h1 - mu) * rstd * gamma[c + 1] + beta[c + 1];
    size_t base = (size_t)r * DMODEL;
    *(float2*)(hn + base + c) = make_float2(v0, v1);
    hnh[(base >> 1) + tid] = f2h2(v0, v1);
}

// ---------------------------------------------------------------------------
extern "C" void kernel_launch(void* const* d_in, const int* in_sizes, int n_in,
                              void* d_out, int out_size)
{
    const float* x   = (const float*)d_in[0];
    const float* Wq  = (const float*)d_in[2];
    const float* bq  = (const float*)d_in[3];
    const float* Wk  = (const float*)d_in[4];
    const float* bk  = (const float*)d_in[5];
    const float* Wv  = (const float*)d_in[6];
    const float* bv  = (const float*)d_in[7];
    const float* lng = (const float*)d_in[14];
    const float* lnb = (const float*)d_in[15];
    const float* W1  = (const float*)d_in[16];
    const float* b1  = (const float*)d_in[17];
    const float* W2  = (const float*)d_in[18];
    const float* b2  = (const float*)d_in[19];

    uint32_t *pxh, *pWqkv, *pW1t, *pW2t, *phnh, *pacth, *pqkvh;
    float *pbqkv, *pattn, *phn;
    cudaGetSymbolAddress((void**)&pxh,    g_xh);
    cudaGetSymbolAddress((void**)&pWqkv,  g_Wqkv);
    cudaGetSymbolAddress((void**)&pW1t,   g_W1t);
    cudaGetSymbolAddress((void**)&pW2t,   g_W2t);
    cudaGetSymbolAddress((void**)&pbqkv,  g_bqkv);
    cudaGetSymbolAddress((void**)&pqkvh,  g_qkvh);
    cudaGetSymbolAddress((void**)&pattn,  g_attn);
    cudaGetSymbolAddress((void**)&phn,    g_hn);
    cudaGetSymbolAddress((void**)&phnh,   g_hnh);
    cudaGetSymbolAddress((void**)&pacth,  g_acth);

    cudaFuncSetAttribute(hgemm2<0>, cudaFuncAttributeMaxDynamicSharedMemorySize, GSMEM);
    cudaFuncSetAttribute(hgemm2<1>, cudaFuncAttributeMaxDynamicSharedMemorySize, GSMEM);
    cudaFuncSetAttribute(hgemm2<2>, cudaFuncAttributeMaxDynamicSharedMemorySize, GSMEM);
    cudaFuncSetAttribute(attn_mma,  cudaFuncAttributeMaxDynamicSharedMemorySize, ASMEM);

    dim3 blk(256);

    // 1: bias  2: x->fp16  3: QKV weight transpose (coalesced)
    prep_bias<<<(QKVN + 255) / 256, blk>>>(bq, bk, bv, pbqkv);
    prep_x<<<(int)(((size_t)MPAD * DMODEL / 2 + 255) / 256), blk>>>(x, pxh);
    prep_wqkv_t<<<dim3(8, 16, 3), blk>>>(Wq, Wk, Wv, pWqkv);

    // 4: fused QKV GEMM  (target for the ncu capture slot)
    hgemm2<0><<<dim3(QKVN / 256, MPAD / 128), blk, GSMEM>>>(
        pxh, pWqkv, pbqkv, nullptr, nullptr, pqkvh, MPAD, QKVN, DMODEL);

    // 5: tensor-core attention
    attn_mma<<<dim3(SEQ / 64, NH, BATCH), dim3(128), ASMEM>>>(pqkvh, pattn);

    // 6: W1 transpose (coalesced)   7: residual + LN   8: W2 transpose
    prep_wt2<<<dim3(8, 64), blk>>>(W1, pW1t, DFF, 256);
    ln_kernel<<<MROWS, blk>>>(x, pattn, lng, lnb, phn, phnh);
    prep_wt2<<<dim3(32, 16), blk>>>(W2, pW2t, DMODEL, 1024);

    // 9: FFN up + gelu -> fp16
    hgemm2<1><<<dim3(DFF / 256, MPAD / 128), blk, GSMEM>>>(
        phnh, pW1t, b1, nullptr, nullptr, pacth, MROWS, DFF, DMODEL);

    // 10: FFN down + bias + residual -> out
    hgemm2<2><<<dim3(DMODEL / 256, MPAD / 128), blk, GSMEM>>>(
        pacth, pW2t, b2, phn, (float*)d_out, nullptr, MROWS, DMODEL, DFF);
}

// round 12
// speedup vs baseline: 4.9553x; 1.1483x over previous
#include <cuda_runtime.h>
#include <cuda_fp16.h>
#include <math.h>
#include <stdint.h>

#define BATCH   2
#define S0      4095
#define SEQ     4096
#define DMODEL  512
#define NH      8
#define DH      64
#define DFF     2048
#define MROWS   (BATCH * S0)    // 8190
#define MPAD    (BATCH * SEQ)   // 8192
#define QKVN    1536
#define QKVW    768             // words per qkv row

// ---------------- scratch ----------------
__device__ __align__(16) uint32_t g_xh[(size_t)MPAD * DMODEL / 2];
__device__ __align__(16) uint32_t g_Wqkv[(size_t)QKVN * DMODEL / 2];
__device__ __align__(16) uint32_t g_W1t[(size_t)DFF * DMODEL / 2];
__device__ __align__(16) uint32_t g_W2t[(size_t)DMODEL * DFF / 2];
__device__ __align__(16) float    g_bqkv[QKVN];
__device__ __align__(16) uint32_t g_qkvh[(size_t)MPAD * QKVW];   // packed fp16
__device__ __align__(16) float    g_attn[(size_t)MPAD * DMODEL];
__device__ __align__(16) float    g_hn[(size_t)MROWS * DMODEL];
__device__ __align__(16) uint32_t g_hnh[(size_t)MROWS * DMODEL / 2];
__device__ __align__(16) uint32_t g_acth[(size_t)MROWS * DFF / 2];

__device__ __forceinline__ uint32_t smem_u32(const void* p) {
    uint32_t a;
    asm("{ .reg .u64 t; cvta.to.shared.u64 t, %1; cvt.u32.u64 %0, t; }"
        : "=r"(a) : "l"(p));
    return a;
}
__device__ __forceinline__ uint32_t f2h2(float a, float b) {
    __half2 h = __floats2half2_rn(a, b);
    return *(uint32_t*)&h;
}
__device__ __forceinline__ float2 h22f2(uint32_t w) {
    __half2 h = *(__half2*)&w;
    return __half22float2(h);
}
__device__ __forceinline__ float gelu_exact(float v) {
    return 0.5f * v * (1.0f + erff(v * 0.70710678118654752440f));
}
__device__ __forceinline__ void mma_f16(float* c, const uint32_t* a,
                                        const uint32_t* b) {
    asm volatile(
        "mma.sync.aligned.m16n8k16.row.col.f32.f16.f16.f32 "
        "{%0,%1,%2,%3}, {%4,%5,%6,%7}, {%8,%9}, {%0,%1,%2,%3};"
        : "+f"(c[0]), "+f"(c[1]), "+f"(c[2]), "+f"(c[3])
        : "r"(a[0]), "r"(a[1]), "r"(a[2]), "r"(a[3]), "r"(b[0]), "r"(b[1]));
}
#define LDSM4(r0, r1, r2, r3, addr) \
    asm volatile("ldmatrix.sync.aligned.m8n8.x4.shared.b16 {%0,%1,%2,%3}, [%4];" \
        : "=r"(r0), "=r"(r1), "=r"(r2), "=r"(r3) : "r"(addr))

__device__ __forceinline__ void cpa16(uint32_t dst, const void* src, bool v) {
    int sz = v ? 16 : 0;
    asm volatile("cp.async.cg.shared.global [%0], [%1], 16, %2;"
        :: "r"(dst), "l"(src), "r"(sz) : "memory");
}

// ---------------------------------------------------------------------------
// fp16 GEMM: C[M,N] = A[M,K] @ B[N,K]^T.  Block 128x128, warp tile 64x32
// (8 warps, 2m x 4n), BK=32, 3-stage cp.async, stride-20-word SMEM, ldmatrix.
// Sized for 2 CTAs/SM (<=128 regs via launch_bounds, 60KB smem).
// GEMM B addressing: lane bit3 -> k-offset, bit4 -> row+8, so B-frag pairs
// are {r0,r1} (rows0-7) and {r2,r3} (rows8-15)  [NOT the attn pairing].
// MODE 0: fp16x2 = acc + bias     MODE 1: fp16x2 = gelu(acc + bias)
// MODE 2: fp32   = acc + bias + res
// ---------------------------------------------------------------------------
#define STGW 5120                 // words per stage: A 2560 + B 2560
#define GSMEM (3 * STGW * 4)      // 61440 bytes

template<int MODE>
__global__ __launch_bounds__(256, 2)
void hgemm2(const uint32_t* __restrict__ A, const uint32_t* __restrict__ B,
            const float* __restrict__ bias, const float* __restrict__ res,
            float* __restrict__ outf, uint32_t* __restrict__ outh,
            int M, int N, int K)
{
    extern __shared__ __align__(16) uint32_t S[];
    const uint32_t sm0 = smem_u32(S);
    const int tid  = threadIdx.x;
    const int lane = tid & 31;
    const int wid  = tid >> 5;
    const int wm   = wid & 1;       // 2 warp-rows x 64
    const int wn   = wid >> 1;      // 4 warp-cols x 32
    const int bn   = blockIdx.x;
    const int bm   = blockIdx.y;
    const int K2   = K >> 1;
    const int NT   = K >> 5;

    const int aRow = wm * 64 + (lane & 15);
    const int aW   = (lane >> 4) << 2;
    const int bRow = wn * 32 + (lane & 7) + ((lane >> 4) << 3);
    const int bW   = ((lane >> 3) & 1) << 2;

    auto load_stage = [&](int kt, int st) {
        const uint32_t base = sm0 + st * (STGW * 4);
#pragma unroll
        for (int i = 0; i < 4; i++) {
            int c = i * 256 + tid;          // 1024 chunks of 16B
            bool isA = (c < 512);
            int idx  = isA ? c : c - 512;
            int row  = idx >> 2, w = idx & 3;
            int grow = (isA ? bm : bn) * 128 + row;
            bool valid = (!isA) || (grow < M);
            const uint32_t* src = (isA ? A : B)
                + (size_t)(valid ? grow : 0) * K2 + kt * 16 + w * 4;
            uint32_t dst = base + ((isA ? 0 : 2560) + row * 20 + w * 4) * 4;
            cpa16(dst, src, valid);
        }
        asm volatile("cp.async.commit_group;" ::: "memory");
    };

    float acc[4][4][4];
#pragma unroll
    for (int i = 0; i < 4; i++)
#pragma unroll
        for (int j = 0; j < 4; j++)
#pragma unroll
            for (int q = 0; q < 4; q++) acc[i][j][q] = 0.0f;

    load_stage(0, 0);
    load_stage(1, 1);

    for (int kt = 0; kt < NT; kt++) {
        if (kt + 1 < NT) asm volatile("cp.async.wait_group 1;" ::: "memory");
        else             asm volatile("cp.async.wait_group 0;" ::: "memory");
        __syncthreads();
        if (kt + 2 < NT) load_stage(kt + 2, (kt + 2) % 3);

        const uint32_t sA = sm0 + (kt % 3) * (STGW * 4);
        const uint32_t sB = sA + 2560 * 4;
#pragma unroll
        for (int kh = 0; kh < 2; kh++) {
            uint32_t a[4][4], b[4][2];
#pragma unroll
            for (int mf = 0; mf < 4; mf++) {
                uint32_t ad = sA + (((aRow + mf * 16) * 20) + aW + kh * 8) * 4;
                LDSM4(a[mf][0], a[mf][1], a[mf][2], a[mf][3], ad);
            }
#pragma unroll
            for (int bp = 0; bp < 2; bp++) {
                uint32_t ad = sB + (((bRow + bp * 16) * 20) + bW + kh * 8) * 4;
                LDSM4(b[2 * bp][0], b[2 * bp][1],
                      b[2 * bp + 1][0], b[2 * bp + 1][1], ad);
            }
#pragma unroll
            for (int mf = 0; mf < 4; mf++)
#pragma unroll
                for (int nf = 0; nf < 4; nf++)
                    mma_f16(acc[mf][nf], a[mf], b[nf]);
        }
    }

#pragma unroll
    for (int mf = 0; mf < 4; mf++) {
#pragma unroll
        for (int nf = 0; nf < 4; nf++) {
            const int r0  = bm * 128 + wm * 64 + mf * 16 + (lane >> 2);
            const int col = bn * 128 + wn * 32 + nf * 8 + (lane & 3) * 2;
            const float b0 = bias[col], b1 = bias[col + 1];
#pragma unroll
            for (int half = 0; half < 2; half++) {
                const int r = r0 + half * 8;
                if (r >= M) continue;
                float v0 = acc[mf][nf][half * 2 + 0] + b0;
                float v1 = acc[mf][nf][half * 2 + 1] + b1;
                if (MODE == 0) {
                    outh[(size_t)r * (N >> 1) + (col >> 1)] = f2h2(v0, v1);
                } else if (MODE == 1) {
                    outh[(size_t)r * (N >> 1) + (col >> 1)] =
                        f2h2(gelu_exact(v0), gelu_exact(v1));
                } else {
                    const float* rr = res + (size_t)r * N + col;
                    *(float2*)&outf[(size_t)r * N + col] =
                        make_float2(v0 + rr[0], v1 + rr[1]);
                }
            }
        }
    }
}

// ---------------------------------------------------------------------------
// prep kernels (coalesced transposes via SMEM tiles)
// ---------------------------------------------------------------------------
__global__ void prep_x(const float* __restrict__ x, uint32_t* __restrict__ o)
{
    size_t idx = (size_t)blockIdx.x * blockDim.x + threadIdx.x;
    if (idx >= (size_t)MPAD * DMODEL / 2) return;
    int r = (int)(idx >> 8), w = (int)(idx & 255);
    int s = r & (SEQ - 1), b = r >> 12;
    float v0 = 0.f, v1 = 0.f;
    if (s < S0) {
        const float* p = x + ((size_t)b * S0 + s) * DMODEL + 2 * w;
        v0 = p[0]; v1 = p[1];
    }
    o[idx] = f2h2(v0, v1);
}

// Transpose W[K][N] (row-major) tile -> out[n][k/2] packed fp16.
__device__ __forceinline__ void wt_tile(const float* __restrict__ W,
                                        uint32_t* __restrict__ o,
                                        int N, int dstStride, int dstRowOff,
                                        float scale, int k0, int n0)
{
    __shared__ float ts[64][33];
    const int tid = threadIdx.x;
#pragma unroll
    for (int i = 0; i < 8; i++) {
        int t = i * 256 + tid;
        int kr = t >> 5, nc = t & 31;
        ts[kr][nc] = W[(size_t)(k0 + kr) * N + n0 + nc];
    }
    __syncthreads();
#pragma unroll
    for (int i = 0; i < 4; i++) {
        int t = i * 256 + tid;
        int n = t >> 5, w = t & 31;
        o[(size_t)(dstRowOff + n0 + n) * dstStride + (k0 >> 1) + w] =
            f2h2(ts[2 * w][n] * scale, ts[2 * w + 1][n] * scale);
    }
}

__global__ __launch_bounds__(256)
void prep_wqkv_t(const float* __restrict__ Wq, const float* __restrict__ Wk,
                 const float* __restrict__ Wv, uint32_t* __restrict__ o)
{
    const int z = blockIdx.z;
    const float* W = (z == 0) ? Wq : (z == 1) ? Wk : Wv;
    float sc = (z == 0) ? 0.125f : 1.0f;
    wt_tile(W, o, DMODEL, 256, z * 512, sc, blockIdx.x * 64, blockIdx.y * 32);
}

__global__ __launch_bounds__(256)
void prep_wt2(const float* __restrict__ W, uint32_t* __restrict__ o,
              int N, int dstStride)
{
    wt_tile(W, o, N, dstStride, 0, 1.0f, blockIdx.x * 64, blockIdx.y * 32);
}

__global__ void prep_bias(const float* __restrict__ bq, const float* __restrict__ bk,
                          const float* __restrict__ bv, float* __restrict__ o)
{
    int n = blockIdx.x * blockDim.x + threadIdx.x;
    if (n >= QKVN) return;
    o[n] = (n < 512) ? bq[n] * 0.125f
         : (n < 1024) ? bk[n - 512] : bv[n - 1024];
}

// ---------------------------------------------------------------------------
// Tensor-core sliding-window attention (unchanged — proven; NOTE its
// ldmatrix addressing differs from the GEMM, so its pairing is {r0,r2}).
// ---------------------------------------------------------------------------
#define AQ0 0
#define AK0 (64 * 72)
#define AV0 (AK0 + 320 * 72)
#define ASMEMH (AV0 + 64 * 328)
#define ASMEM (ASMEMH * 2)

__global__ __launch_bounds__(128, 1)
void attn_mma(const uint32_t* __restrict__ qkvh, float* __restrict__ out)
{
    extern __shared__ __align__(16) unsigned short SH[];
    const uint32_t sb = smem_u32(SH);
    const int tid  = threadIdx.x;
    const int lane = tid & 31;
    const int w    = tid >> 5;
    const int h    = blockIdx.y;
    const int b    = blockIdx.z;
    const int t0   = blockIdx.x * 64;
    const size_t rowbase = (size_t)b * SEQ;

#pragma unroll
    for (int i = 0; i < 4; i++) {
        int c = i * 128 + tid;
        int row = c >> 3, c16 = c & 7;
        const uint32_t* src = qkvh + (rowbase + t0 + row) * QKVW + h * 32 + c16 * 4;
        *(uint4*)&SH[AQ0 + row * 72 + c16 * 8] = *(const uint4*)src;
    }
#pragma unroll
    for (int i = 0; i < 20; i++) {
        int c = i * 128 + tid;
        int row = c >> 3, c16 = c & 7;
        int key = t0 - 128 + row;
        key = key < 0 ? 0 : (key > SEQ - 1 ? SEQ - 1 : key);
        const uint32_t* src = qkvh + (rowbase + key) * QKVW + 256 + h * 32 + c16 * 4;
        *(uint4*)&SH[AK0 + row * 72 + c16 * 8] = *(const uint4*)src;
    }
#pragma unroll
    for (int i = 0; i < 20; i++) {
        int c = i * 128 + tid;
        int row = c >> 3, c16 = c & 7;
        int key = t0 - 128 + row;
        key = key < 0 ? 0 : (key > SEQ - 1 ? SEQ - 1 : key);
        const uint32_t* src = qkvh + (rowbase + key) * QKVW + 512 + h * 32 + c16 * 4;
        uint4 v = *(const uint4*)src;
        const unsigned short* hv = (const unsigned short*)&v;
#pragma unroll
        for (int j = 0; j < 8; j++)
            SH[AV0 + (c16 * 8 + j) * 328 + row] = hv[j];
    }
    __syncthreads();

    const int l15 = lane & 15;
    const int lh8 = (lane >> 4) << 3;
    const int kl0 = (lane & 3) << 1;
    const int r   = 16 * w + (lane >> 2);

    uint32_t aq[4][4];
#pragma unroll
    for (int j = 0; j < 4; j++) {
        uint32_t ad = sb + ((16 * w + l15) * 72 + 16 * j + lh8) * 2;
        LDSM4(aq[j][0], aq[j][1], aq[j][2], aq[j][3], ad);
    }

    float od[8][4];
#pragma unroll
    for (int nf = 0; nf < 8; nf++)
#pragma unroll
        for (int q = 0; q < 4; q++) od[nf][q] = 0.0f;
    float m0 = -1e30f, m1 = -1e30f, l0 = 0.f, l1 = 0.f;

    for (int c = 0; c < 5; c++) {
        const int ks = t0 - 128 + 64 * c;
        if (ks + 63 < 0 || ks > S0 - 1) continue;

        float sc[8][4];
#pragma unroll
        for (int nf = 0; nf < 8; nf++)
#pragma unroll
            for (int q = 0; q < 4; q++) sc[nf][q] = 0.0f;

#pragma unroll
        for (int j = 0; j < 4; j++)
#pragma unroll
            for (int p = 0; p < 4; p++) {
                uint32_t r0, r1, r2, r3;
                uint32_t ad = sb + (AK0 + (c * 64 + 16 * p + l15) * 72
                                    + 16 * j + lh8) * 2;
                LDSM4(r0, r1, r2, r3, ad);
                uint32_t b0[2] = {r0, r2}, b1[2] = {r1, r3};
                mma_f16(sc[2 * p],     aq[j], b0);
                mma_f16(sc[2 * p + 1], aq[j], b1);
            }

        float mx0 = -1e30f, mx1 = -1e30f;
#pragma unroll
        for (int nf = 0; nf < 8; nf++) {
            int kl = 8 * nf + kl0;
            int u  = 64 * c + kl - r;
            int sg = ks + kl;
            bool k0ok = (sg >= 0) && (sg < S0);
            bool k1ok = (sg + 1 >= 0) && (sg + 1 < S0);
            bool v0 = k0ok && (u >= 0)     && (u <= 256);
            bool v1 = k1ok && (u + 1 >= 0) && (u + 1 <= 256);
            bool v2 = k0ok && (u - 8 >= 0) && (u - 8 <= 256);
            bool v3 = k1ok && (u - 7 >= 0) && (u - 7 <= 256);
            sc[nf][0] = v0 ? sc[nf][0] : -1e30f;
            sc[nf][1] = v1 ? sc[nf][1] : -1e30f;
            sc[nf][2] = v2 ? sc[nf][2] : -1e30f;
            sc[nf][3] = v3 ? sc[nf][3] : -1e30f;
            mx0 = fmaxf(mx0, fmaxf(sc[nf][0], sc[nf][1]));
            mx1 = fmaxf(mx1, fmaxf(sc[nf][2], sc[nf][3]));
        }
        mx0 = fmaxf(mx0, __shfl_xor_sync(0xffffffffu, mx0, 1));
        mx0 = fmaxf(mx0, __shfl_xor_sync(0xffffffffu, mx0, 2));
        mx1 = fmaxf(mx1, __shfl_xor_sync(0xffffffffu, mx1, 1));
        mx1 = fmaxf(mx1, __shfl_xor_sync(0xffffffffu, mx1, 2));

        float mn0 = fmaxf(m0, mx0), mn1 = fmaxf(m1, mx1);
        float s0 = __expf(m0 - mn0), s1 = __expf(m1 - mn1);
        float ls0 = 0.f, ls1 = 0.f;
        uint32_t pa[4][4];
#pragma unroll
        for (int nf = 0; nf < 8; nf++) {
            float e0 = __expf(sc[nf][0] - mn0);
            float e1 = __expf(sc[nf][1] - mn0);
            float e2 = __expf(sc[nf][2] - mn1);
            float e3 = __expf(sc[nf][3] - mn1);
            ls0 += e0 + e1; ls1 += e2 + e3;
            int j = nf >> 1, q = nf & 1;
            pa[j][2 * q]     = f2h2(e0, e1);
            pa[j][2 * q + 1] = f2h2(e2, e3);
        }
        ls0 += __shfl_xor_sync(0xffffffffu, ls0, 1);
        ls0 += __shfl_xor_sync(0xffffffffu, ls0, 2);
        ls1 += __shfl_xor_sync(0xffffffffu, ls1, 1);
        ls1 += __shfl_xor_sync(0xffffffffu, ls1, 2);
        l0 = l0 * s0 + ls0;
        l1 = l1 * s1 + ls1;
        m0 = mn0; m1 = mn1;
#pragma unroll
        for (int nf = 0; nf < 8; nf++) {
            od[nf][0] *= s0; od[nf][1] *= s0;
            od[nf][2] *= s1; od[nf][3] *= s1;
        }

#pragma unroll
        for (int j = 0; j < 4; j++)
#pragma unroll
            for (int p = 0; p < 4; p++) {
                uint32_t r0, r1, r2, r3;
                uint32_t ad = sb + (AV0 + (16 * p + l15) * 328
                                    + c * 64 + 16 * j + lh8) * 2;
                LDSM4(r0, r1, r2, r3, ad);
                uint32_t b0[2] = {r0, r2}, b1[2] = {r1, r3};
                mma_f16(od[2 * p],     pa[j], b0);
                mma_f16(od[2 * p + 1], pa[j], b1);
            }
    }

    {
        const uint32_t* kg = qkvh + (rowbase + SEQ - 1) * QKVW + 256 + h * 32
                           + (lane & 3) * 8;
        const uint32_t* q0 = (const uint32_t*)(SH + (size_t)(AQ0 + r * 72))
                           + (lane & 3) * 8;
        const uint32_t* q1 = (const uint32_t*)(SH + (size_t)(AQ0 + (r + 8) * 72))
                           + (lane & 3) * 8;
        float gs0 = 0.f, gs1 = 0.f;
#pragma unroll
        for (int i = 0; i < 8; i++) {
            float2 fk = h22f2(kg[i]);
            float2 f0 = h22f2(q0[i]);
            float2 f1 = h22f2(q1[i]);
            gs0 += f0.x * fk.x + f0.y * fk.y;
            gs1 += f1.x * fk.x + f1.y * fk.y;
        }
        gs0 += __shfl_xor_sync(0xffffffffu, gs0, 1);
        gs0 += __shfl_xor_sync(0xffffffffu, gs0, 2);
        gs1 += __shfl_xor_sync(0xffffffffu, gs1, 1);
        gs1 += __shfl_xor_sync(0xffffffffu, gs1, 2);

        float mn0 = fmaxf(m0, gs0), mn1 = fmaxf(m1, gs1);
        float s0 = __expf(m0 - mn0), s1 = __expf(m1 - mn1);
        float pg0 = __expf(gs0 - mn0), pg1 = __expf(gs1 - mn1);
        l0 = l0 * s0 + pg0;
        l1 = l1 * s1 + pg1;
        const uint32_t* vg = qkvh + (rowbase + SEQ - 1) * QKVW + 512 + h * 32
                           + (lane & 3);
#pragma unroll
        for (int nf = 0; nf < 8; nf++) {
            float2 fv = h22f2(vg[nf * 4]);
            od[nf][0] = od[nf][0] * s0 + pg0 * fv.x;
            od[nf][1] = od[nf][1] * s0 + pg0 * fv.y;
            od[nf][2] = od[nf][2] * s1 + pg1 * fv.x;
            od[nf][3] = od[nf][3] * s1 + pg1 * fv.y;
        }
    }

    const float inv0 = 1.0f / l0, inv1 = 1.0f / l1;
    const int t = t0 + r;
    float* o0 = out + ((size_t)b * SEQ + t) * DMODEL + h * DH + kl0;
    float* o1 = o0 + 8 * (size_t)DMODEL;
#pragma unroll
    for (int nf = 0; nf < 8; nf++) {
        *(float2*)(o0 + nf * 8) = make_float2(od[nf][0] * inv0, od[nf][1] * inv0);
        *(float2*)(o1 + nf * 8) = make_float2(od[nf][2] * inv1, od[nf][3] * inv1);
    }
}

// ---------------------------------------------------------------------------
// Residual + LayerNorm -> hn fp32 + packed fp16
// ---------------------------------------------------------------------------
__global__ __launch_bounds__(256)
void ln_kernel(const float* __restrict__ x, const float* __restrict__ attn,
               const float* __restrict__ gamma, const float* __restrict__ beta,
               float* __restrict__ hn, uint32_t* __restrict__ hnh)
{
    const int r = blockIdx.x;
    const int b = r / S0;
    const int s = r - b * S0;
    const int tid = threadIdx.x;
    const int c = tid * 2;

    float2 xv = *(const float2*)(x + (size_t)r * DMODEL + c);
    float2 av = *(const float2*)(attn + ((size_t)b * SEQ + s) * DMODEL + c);
    float h0 = xv.x + av.x;
    float h1 = xv.y + av.y;
    float sum = h0 + h1;
    float sq  = h0 * h0 + h1 * h1;
#pragma unroll
    for (int off = 16; off; off >>= 1) {
        sum += __shfl_xor_sync(0xffffffffu, sum, off);
        sq  += __shfl_xor_sync(0xffffffffu, sq,  off);
    }
    __shared__ float rs[8], rq[8];
    int w = tid >> 5, lane = tid & 31;
    if (lane == 0) { rs[w] = sum; rq[w] = sq; }
    __syncthreads();
    float ts = 0.f, tq = 0.f;
#pragma unroll
    for (int i = 0; i < 8; i++) { ts += rs[i]; tq += rq[i]; }
    float mu   = ts * (1.0f / DMODEL);
    float var  = tq * (1.0f / DMODEL) - mu * mu;
    float rstd = rsqrtf(var + 1e-5f);
    float v0 = (h0 - mu) * rstd * gamma[c]     + beta[c];
    float v1 = (h1 - mu) * rstd * gamma[c + 1] + beta[c + 1];
    size_t base = (size_t)r * DMODEL;
    *(float2*)(hn + base + c) = make_float2(v0, v1);
    hnh[(base >> 1) + tid] = f2h2(v0, v1);
}

// ---------------------------------------------------------------------------
extern "C" void kernel_launch(void* const* d_in, const int* in_sizes, int n_in,
                              void* d_out, int out_size)
{
    const float* x   = (const float*)d_in[0];
    const float* Wq  = (const float*)d_in[2];
    const float* bq  = (const float*)d_in[3];
    const float* Wk  = (const float*)d_in[4];
    const float* bk  = (const float*)d_in[5];
    const float* Wv  = (const float*)d_in[6];
    const float* bv  = (const float*)d_in[7];
    const float* lng = (const float*)d_in[14];
    const float* lnb = (const float*)d_in[15];
    const float* W1  = (const float*)d_in[16];
    const float* b1  = (const float*)d_in[17];
    const float* W2  = (const float*)d_in[18];
    const float* b2  = (const float*)d_in[19];

    uint32_t *pxh, *pWqkv, *pW1t, *pW2t, *phnh, *pacth, *pqkvh;
    float *pbqkv, *pattn, *phn;
    cudaGetSymbolAddress((void**)&pxh,    g_xh);
    cudaGetSymbolAddress((void**)&pWqkv,  g_Wqkv);
    cudaGetSymbolAddress((void**)&pW1t,   g_W1t);
    cudaGetSymbolAddress((void**)&pW2t,   g_W2t);
    cudaGetSymbolAddress((void**)&pbqkv,  g_bqkv);
    cudaGetSymbolAddress((void**)&pqkvh,  g_qkvh);
    cudaGetSymbolAddress((void**)&pattn,  g_attn);
    cudaGetSymbolAddress((void**)&phn,    g_hn);
    cudaGetSymbolAddress((void**)&phnh,   g_hnh);
    cudaGetSymbolAddress((void**)&pacth,  g_acth);

    cudaFuncSetAttribute(hgemm2<0>, cudaFuncAttributeMaxDynamicSharedMemorySize, GSMEM);
    cudaFuncSetAttribute(hgemm2<1>, cudaFuncAttributeMaxDynamicSharedMemorySize, GSMEM);
    cudaFuncSetAttribute(hgemm2<2>, cudaFuncAttributeMaxDynamicSharedMemorySize, GSMEM);
    cudaFuncSetAttribute(attn_mma,  cudaFuncAttributeMaxDynamicSharedMemorySize, ASMEM);

    dim3 blk(256);

    // 1: bias  2: x->fp16  3: QKV weight transpose
    prep_bias<<<(QKVN + 255) / 256, blk>>>(bq, bk, bv, pbqkv);
    prep_x<<<(int)(((size_t)MPAD * DMODEL / 2 + 255) / 256), blk>>>(x, pxh);
    prep_wqkv_t<<<dim3(8, 16, 3), blk>>>(Wq, Wk, Wv, pWqkv);

    // 4: fused QKV GEMM (ncu target slot)
    hgemm2<0><<<dim3(QKVN / 128, MPAD / 128), blk, GSMEM>>>(
        pxh, pWqkv, pbqkv, nullptr, nullptr, pqkvh, MPAD, QKVN, DMODEL);

    // 5: tensor-core attention
    attn_mma<<<dim3(SEQ / 64, NH, BATCH), dim3(128), ASMEM>>>(pqkvh, pattn);

    // 6: W1 transpose  7: residual + LN  8: W2 transpose
    prep_wt2<<<dim3(8, 64), blk>>>(W1, pW1t, DFF, 256);
    ln_kernel<<<MROWS, blk>>>(x, pattn, lng, lnb, phn, phnh);
    prep_wt2<<<dim3(32, 16), blk>>>(W2, pW2t, DMODEL, 1024);

    // 9: FFN up + gelu -> fp16
    hgemm2<1><<<dim3(DFF / 128, MPAD / 128), blk, GSMEM>>>(
        phnh, pW1t, b1, nullptr, nullptr, pacth, MROWS, DFF, DMODEL);

    // 10: FFN down + bias + residual -> out
    hgemm2<2><<<dim3(DMODEL / 128, MPAD / 128), blk, GSMEM>>>(
        pacth, pW2t, b2, phn, (float*)d_out, nullptr, MROWS, DMODEL, DFF);
}

// round 13
// speedup vs baseline: 5.0006x; 1.0091x over previous
#include <cuda_runtime.h>
#include <cuda_fp16.h>
#include <math.h>
#include <stdint.h>

#define BATCH   2
#define S0      4095
#define SEQ     4096
#define DMODEL  512
#define NH      8
#define DH      64
#define DFF     2048
#define MROWS   (BATCH * S0)    // 8190
#define MPAD    (BATCH * SEQ)   // 8192
#define QKVN    1536
#define QKVW    768             // words per qkv row

// ---------------- scratch ----------------
__device__ __align__(16) uint32_t g_xh[(size_t)MPAD * DMODEL / 2];
__device__ __align__(16) uint32_t g_Wqkv[(size_t)QKVN * DMODEL / 2];
__device__ __align__(16) uint32_t g_W1t[(size_t)DFF * DMODEL / 2];
__device__ __align__(16) uint32_t g_W2t[(size_t)DMODEL * DFF / 2];
__device__ __align__(16) float    g_bqkv[QKVN];
__device__ __align__(16) uint32_t g_qkvh[(size_t)MPAD * QKVW];   // packed fp16
__device__ __align__(16) float    g_attn[(size_t)MPAD * DMODEL];
__device__ __align__(16) float    g_hn[(size_t)MROWS * DMODEL];
__device__ __align__(16) uint32_t g_hnh[(size_t)MROWS * DMODEL / 2];
__device__ __align__(16) uint32_t g_acth[(size_t)MROWS * DFF / 2];

__device__ __forceinline__ uint32_t smem_u32(const void* p) {
    uint32_t a;
    asm("{ .reg .u64 t; cvta.to.shared.u64 t, %1; cvt.u32.u64 %0, t; }"
        : "=r"(a) : "l"(p));
    return a;
}
__device__ __forceinline__ uint32_t f2h2(float a, float b) {
    __half2 h = __floats2half2_rn(a, b);
    return *(uint32_t*)&h;
}
__device__ __forceinline__ float2 h22f2(uint32_t w) {
    __half2 h = *(__half2*)&w;
    return __half22float2(h);
}
__device__ __forceinline__ float gelu_exact(float v) {
    return 0.5f * v * (1.0f + erff(v * 0.70710678118654752440f));
}
__device__ __forceinline__ void mma_f16(float* c, const uint32_t* a,
                                        const uint32_t* b) {
    asm volatile(
        "mma.sync.aligned.m16n8k16.row.col.f32.f16.f16.f32 "
        "{%0,%1,%2,%3}, {%4,%5,%6,%7}, {%8,%9}, {%0,%1,%2,%3};"
        : "+f"(c[0]), "+f"(c[1]), "+f"(c[2]), "+f"(c[3])
        : "r"(a[0]), "r"(a[1]), "r"(a[2]), "r"(a[3]), "r"(b[0]), "r"(b[1]));
}
#define LDSM4(r0, r1, r2, r3, addr) \
    asm volatile("ldmatrix.sync.aligned.m8n8.x4.shared.b16 {%0,%1,%2,%3}, [%4];" \
        : "=r"(r0), "=r"(r1), "=r"(r2), "=r"(r3) : "r"(addr))

__device__ __forceinline__ void cpa16(uint32_t dst, const void* src, bool v) {
    int sz = v ? 16 : 0;
    asm volatile("cp.async.cg.shared.global [%0], [%1], 16, %2;"
        :: "r"(dst), "l"(src), "r"(sz) : "memory");
}

// ---------------------------------------------------------------------------
// fp16 GEMM: C[M,N] = A[M,K] @ B[N,K]^T.  Block 128x128, warp tile 64x32
// (8 warps, 2m x 4n), BK=32, 4-stage cp.async (wait_group 2), stride-20-word
// SMEM, ldmatrix operands. 2 CTAs/SM (126 regs, 80KB smem).
// GEMM B addressing: lane bit3 -> k-offset, bit4 -> row+8, so B-frag pairs
// are {r0,r1} (rows0-7) and {r2,r3} (rows8-15)  [NOT the attn pairing].
// MODE 0: fp16x2 = acc + bias     MODE 1: fp16x2 = gelu(acc + bias)
// MODE 2: fp32   = acc + bias + res
// ---------------------------------------------------------------------------
#define STGW 5120                 // words per stage: A 2560 + B 2560
#define GSTAGES 4
#define GSMEM (GSTAGES * STGW * 4)   // 81920 bytes

template<int MODE>
__global__ __launch_bounds__(256, 2)
void hgemm2(const uint32_t* __restrict__ A, const uint32_t* __restrict__ B,
            const float* __restrict__ bias, const float* __restrict__ res,
            float* __restrict__ outf, uint32_t* __restrict__ outh,
            int M, int N, int K)
{
    extern __shared__ __align__(16) uint32_t S[];
    const uint32_t sm0 = smem_u32(S);
    const int tid  = threadIdx.x;
    const int lane = tid & 31;
    const int wid  = tid >> 5;
    const int wm   = wid & 1;       // 2 warp-rows x 64
    const int wn   = wid >> 1;      // 4 warp-cols x 32
    const int bn   = blockIdx.x;
    const int bm   = blockIdx.y;
    const int K2   = K >> 1;
    const int NT   = K >> 5;

    const int aRow = wm * 64 + (lane & 15);
    const int aW   = (lane >> 4) << 2;
    const int bRow = wn * 32 + (lane & 7) + ((lane >> 4) << 3);
    const int bW   = ((lane >> 3) & 1) << 2;

    auto load_stage = [&](int kt, int st) {
        const uint32_t base = sm0 + st * (STGW * 4);
#pragma unroll
        for (int i = 0; i < 4; i++) {
            int c = i * 256 + tid;          // 1024 chunks of 16B
            bool isA = (c < 512);
            int idx  = isA ? c : c - 512;
            int row  = idx >> 2, w = idx & 3;
            int grow = (isA ? bm : bn) * 128 + row;
            bool valid = (!isA) || (grow < M);
            const uint32_t* src = (isA ? A : B)
                + (size_t)(valid ? grow : 0) * K2 + kt * 16 + w * 4;
            uint32_t dst = base + ((isA ? 0 : 2560) + row * 20 + w * 4) * 4;
            cpa16(dst, src, valid);
        }
        asm volatile("cp.async.commit_group;" ::: "memory");
    };

    float acc[4][4][4];
#pragma unroll
    for (int i = 0; i < 4; i++)
#pragma unroll
        for (int j = 0; j < 4; j++)
#pragma unroll
            for (int q = 0; q < 4; q++) acc[i][j][q] = 0.0f;

    load_stage(0, 0);
    if (NT > 1) load_stage(1, 1);
    if (NT > 2) load_stage(2, 2);

    for (int kt = 0; kt < NT; kt++) {
        // committed so far: loads 0..min(kt+2, NT-1). Guarantee stage kt done:
        if (kt + 2 < NT)      asm volatile("cp.async.wait_group 2;" ::: "memory");
        else if (kt + 1 < NT) asm volatile("cp.async.wait_group 1;" ::: "memory");
        else                  asm volatile("cp.async.wait_group 0;" ::: "memory");
        __syncthreads();
        if (kt + 3 < NT) load_stage(kt + 3, (kt + 3) % GSTAGES);

        const uint32_t sA = sm0 + (kt % GSTAGES) * (STGW * 4);
        const uint32_t sB = sA + 2560 * 4;
#pragma unroll
        for (int kh = 0; kh < 2; kh++) {
            uint32_t a[4][4], b[4][2];
#pragma unroll
            for (int mf = 0; mf < 4; mf++) {
                uint32_t ad = sA + (((aRow + mf * 16) * 20) + aW + kh * 8) * 4;
                LDSM4(a[mf][0], a[mf][1], a[mf][2], a[mf][3], ad);
            }
#pragma unroll
            for (int bp = 0; bp < 2; bp++) {
                uint32_t ad = sB + (((bRow + bp * 16) * 20) + bW + kh * 8) * 4;
                LDSM4(b[2 * bp][0], b[2 * bp][1],
                      b[2 * bp + 1][0], b[2 * bp + 1][1], ad);
            }
#pragma unroll
            for (int mf = 0; mf < 4; mf++)
#pragma unroll
                for (int nf = 0; nf < 4; nf++)
                    mma_f16(acc[mf][nf], a[mf], b[nf]);
        }
    }

#pragma unroll
    for (int mf = 0; mf < 4; mf++) {
#pragma unroll
        for (int nf = 0; nf < 4; nf++) {
            const int r0  = bm * 128 + wm * 64 + mf * 16 + (lane >> 2);
            const int col = bn * 128 + wn * 32 + nf * 8 + (lane & 3) * 2;
            const float b0 = bias[col], b1 = bias[col + 1];
#pragma unroll
            for (int half = 0; half < 2; half++) {
                const int r = r0 + half * 8;
                if (r >= M) continue;
                float v0 = acc[mf][nf][half * 2 + 0] + b0;
                float v1 = acc[mf][nf][half * 2 + 1] + b1;
                if (MODE == 0) {
                    outh[(size_t)r * (N >> 1) + (col >> 1)] = f2h2(v0, v1);
                } else if (MODE == 1) {
                    outh[(size_t)r * (N >> 1) + (col >> 1)] =
                        f2h2(gelu_exact(v0), gelu_exact(v1));
                } else {
                    const float* rr = res + (size_t)r * N + col;
                    *(float2*)&outf[(size_t)r * N + col] =
                        make_float2(v0 + rr[0], v1 + rr[1]);
                }
            }
        }
    }
}

// ---------------------------------------------------------------------------
// prep kernels (coalesced transposes via SMEM tiles)
// ---------------------------------------------------------------------------
__global__ void prep_x(const float* __restrict__ x, uint32_t* __restrict__ o)
{
    size_t idx = (size_t)blockIdx.x * blockDim.x + threadIdx.x;
    if (idx >= (size_t)MPAD * DMODEL / 2) return;
    int r = (int)(idx >> 8), w = (int)(idx & 255);
    int s = r & (SEQ - 1), b = r >> 12;
    float v0 = 0.f, v1 = 0.f;
    if (s < S0) {
        const float* p = x + ((size_t)b * S0 + s) * DMODEL + 2 * w;
        v0 = p[0]; v1 = p[1];
    }
    o[idx] = f2h2(v0, v1);
}

// Transpose W[K][N] (row-major) tile -> out[n][k/2] packed fp16.
__device__ __forceinline__ void wt_tile(const float* __restrict__ W,
                                        uint32_t* __restrict__ o,
                                        int N, int dstStride, int dstRowOff,
                                        float scale, int k0, int n0)
{
    __shared__ float ts[64][33];
    const int tid = threadIdx.x;
#pragma unroll
    for (int i = 0; i < 8; i++) {
        int t = i * 256 + tid;
        int kr = t >> 5, nc = t & 31;
        ts[kr][nc] = W[(size_t)(k0 + kr) * N + n0 + nc];
    }
    __syncthreads();
#pragma unroll
    for (int i = 0; i < 4; i++) {
        int t = i * 256 + tid;
        int n = t >> 5, w = t & 31;
        o[(size_t)(dstRowOff + n0 + n) * dstStride + (k0 >> 1) + w] =
            f2h2(ts[2 * w][n] * scale, ts[2 * w + 1][n] * scale);
    }
}

__global__ __launch_bounds__(256)
void prep_wqkv_t(const float* __restrict__ Wq, const float* __restrict__ Wk,
                 const float* __restrict__ Wv, uint32_t* __restrict__ o)
{
    const int z = blockIdx.z;
    const float* W = (z == 0) ? Wq : (z == 1) ? Wk : Wv;
    float sc = (z == 0) ? 0.125f : 1.0f;
    wt_tile(W, o, DMODEL, 256, z * 512, sc, blockIdx.x * 64, blockIdx.y * 32);
}

__global__ __launch_bounds__(256)
void prep_wt2(const float* __restrict__ W, uint32_t* __restrict__ o,
              int N, int dstStride)
{
    wt_tile(W, o, N, dstStride, 0, 1.0f, blockIdx.x * 64, blockIdx.y * 32);
}

__global__ void prep_bias(const float* __restrict__ bq, const float* __restrict__ bk,
                          const float* __restrict__ bv, float* __restrict__ o)
{
    int n = blockIdx.x * blockDim.x + threadIdx.x;
    if (n >= QKVN) return;
    o[n] = (n < 512) ? bq[n] * 0.125f
         : (n < 1024) ? bk[n - 512] : bv[n - 1024];
}

// ---------------------------------------------------------------------------
// Tensor-core sliding-window attention (unchanged — proven; its ldmatrix
// addressing differs from the GEMM, so its B pairing {r0,r2} is correct).
// ---------------------------------------------------------------------------
#define AQ0 0
#define AK0 (64 * 72)
#define AV0 (AK0 + 320 * 72)
#define ASMEMH (AV0 + 64 * 328)
#define ASMEM (ASMEMH * 2)

__global__ __launch_bounds__(128, 1)
void attn_mma(const uint32_t* __restrict__ qkvh, float* __restrict__ out)
{
    extern __shared__ __align__(16) unsigned short SH[];
    const uint32_t sb = smem_u32(SH);
    const int tid  = threadIdx.x;
    const int lane = tid & 31;
    const int w    = tid >> 5;
    const int h    = blockIdx.y;
    const int b    = blockIdx.z;
    const int t0   = blockIdx.x * 64;
    const size_t rowbase = (size_t)b * SEQ;

#pragma unroll
    for (int i = 0; i < 4; i++) {
        int c = i * 128 + tid;
        int row = c >> 3, c16 = c & 7;
        const uint32_t* src = qkvh + (rowbase + t0 + row) * QKVW + h * 32 + c16 * 4;
        *(uint4*)&SH[AQ0 + row * 72 + c16 * 8] = *(const uint4*)src;
    }
#pragma unroll
    for (int i = 0; i < 20; i++) {
        int c = i * 128 + tid;
        int row = c >> 3, c16 = c & 7;
        int key = t0 - 128 + row;
        key = key < 0 ? 0 : (key > SEQ - 1 ? SEQ - 1 : key);
        const uint32_t* src = qkvh + (rowbase + key) * QKVW + 256 + h * 32 + c16 * 4;
        *(uint4*)&SH[AK0 + row * 72 + c16 * 8] = *(const uint4*)src;
    }
#pragma unroll
    for (int i = 0; i < 20; i++) {
        int c = i * 128 + tid;
        int row = c >> 3, c16 = c & 7;
        int key = t0 - 128 + row;
        key = key < 0 ? 0 : (key > SEQ - 1 ? SEQ - 1 : key);
        const uint32_t* src = qkvh + (rowbase + key) * QKVW + 512 + h * 32 + c16 * 4;
        uint4 v = *(const uint4*)src;
        const unsigned short* hv = (const unsigned short*)&v;
#pragma unroll
        for (int j = 0; j < 8; j++)
            SH[AV0 + (c16 * 8 + j) * 328 + row] = hv[j];
    }
    __syncthreads();

    const int l15 = lane & 15;
    const int lh8 = (lane >> 4) << 3;
    const int kl0 = (lane & 3) << 1;
    const int r   = 16 * w + (lane >> 2);

    uint32_t aq[4][4];
#pragma unroll
    for (int j = 0; j < 4; j++) {
        uint32_t ad = sb + ((16 * w + l15) * 72 + 16 * j + lh8) * 2;
        LDSM4(aq[j][0], aq[j][1], aq[j][2], aq[j][3], ad);
    }

    float od[8][4];
#pragma unroll
    for (int nf = 0; nf < 8; nf++)
#pragma unroll
        for (int q = 0; q < 4; q++) od[nf][q] = 0.0f;
    float m0 = -1e30f, m1 = -1e30f, l0 = 0.f, l1 = 0.f;

    for (int c = 0; c < 5; c++) {
        const int ks = t0 - 128 + 64 * c;
        if (ks + 63 < 0 || ks > S0 - 1) continue;

        float sc[8][4];
#pragma unroll
        for (int nf = 0; nf < 8; nf++)
#pragma unroll
            for (int q = 0; q < 4; q++) sc[nf][q] = 0.0f;

#pragma unroll
        for (int j = 0; j < 4; j++)
#pragma unroll
            for (int p = 0; p < 4; p++) {
                uint32_t r0, r1, r2, r3;
                uint32_t ad = sb + (AK0 + (c * 64 + 16 * p + l15) * 72
                                    + 16 * j + lh8) * 2;
                LDSM4(r0, r1, r2, r3, ad);
                uint32_t b0[2] = {r0, r2}, b1[2] = {r1, r3};
                mma_f16(sc[2 * p],     aq[j], b0);
                mma_f16(sc[2 * p + 1], aq[j], b1);
            }

        float mx0 = -1e30f, mx1 = -1e30f;
#pragma unroll
        for (int nf = 0; nf < 8; nf++) {
            int kl = 8 * nf + kl0;
            int u  = 64 * c + kl - r;
            int sg = ks + kl;
            bool k0ok = (sg >= 0) && (sg < S0);
            bool k1ok = (sg + 1 >= 0) && (sg + 1 < S0);
            bool v0 = k0ok && (u >= 0)     && (u <= 256);
            bool v1 = k1ok && (u + 1 >= 0) && (u + 1 <= 256);
            bool v2 = k0ok && (u - 8 >= 0) && (u - 8 <= 256);
            bool v3 = k1ok && (u - 7 >= 0) && (u - 7 <= 256);
            sc[nf][0] = v0 ? sc[nf][0] : -1e30f;
            sc[nf][1] = v1 ? sc[nf][1] : -1e30f;
            sc[nf][2] = v2 ? sc[nf][2] : -1e30f;
            sc[nf][3] = v3 ? sc[nf][3] : -1e30f;
            mx0 = fmaxf(mx0, fmaxf(sc[nf][0], sc[nf][1]));
            mx1 = fmaxf(mx1, fmaxf(sc[nf][2], sc[nf][3]));
        }
        mx0 = fmaxf(mx0, __shfl_xor_sync(0xffffffffu, mx0, 1));
        mx0 = fmaxf(mx0, __shfl_xor_sync(0xffffffffu, mx0, 2));
        mx1 = fmaxf(mx1, __shfl_xor_sync(0xffffffffu, mx1, 1));
        mx1 = fmaxf(mx1, __shfl_xor_sync(0xffffffffu, mx1, 2));

        float mn0 = fmaxf(m0, mx0), mn1 = fmaxf(m1, mx1);
        float s0 = __expf(m0 - mn0), s1 = __expf(m1 - mn1);
        float ls0 = 0.f, ls1 = 0.f;
        uint32_t pa[4][4];
#pragma unroll
        for (int nf = 0; nf < 8; nf++) {
            float e0 = __expf(sc[nf][0] - mn0);
            float e1 = __expf(sc[nf][1] - mn0);
            float e2 = __expf(sc[nf][2] - mn1);
            float e3 = __expf(sc[nf][3] - mn1);
            ls0 += e0 + e1; ls1 += e2 + e3;
            int j = nf >> 1, q = nf & 1;
            pa[j][2 * q]     = f2h2(e0, e1);
            pa[j][2 * q + 1] = f2h2(e2, e3);
        }
        ls0 += __shfl_xor_sync(0xffffffffu, ls0, 1);
        ls0 += __shfl_xor_sync(0xffffffffu, ls0, 2);
        ls1 += __shfl_xor_sync(0xffffffffu, ls1, 1);
        ls1 += __shfl_xor_sync(0xffffffffu, ls1, 2);
        l0 = l0 * s0 + ls0;
        l1 = l1 * s1 + ls1;
        m0 = mn0; m1 = mn1;
#pragma unroll
        for (int nf = 0; nf < 8; nf++) {
            od[nf][0] *= s0; od[nf][1] *= s0;
            od[nf][2] *= s1; od[nf][3] *= s1;
        }

#pragma unroll
        for (int j = 0; j < 4; j++)
#pragma unroll
            for (int p = 0; p < 4; p++) {
                uint32_t r0, r1, r2, r3;
                uint32_t ad = sb + (AV0 + (16 * p + l15) * 328
                                    + c * 64 + 16 * j + lh8) * 2;
                LDSM4(r0, r1, r2, r3, ad);
                uint32_t b0[2] = {r0, r2}, b1[2] = {r1, r3};
                mma_f16(od[2 * p],     pa[j], b0);
                mma_f16(od[2 * p + 1], pa[j], b1);
            }
    }

    {
        const uint32_t* kg = qkvh + (rowbase + SEQ - 1) * QKVW + 256 + h * 32
                           + (lane & 3) * 8;
        const uint32_t* q0 = (const uint32_t*)(SH + (size_t)(AQ0 + r * 72))
                           + (lane & 3) * 8;
        const uint32_t* q1 = (const uint32_t*)(SH + (size_t)(AQ0 + (r + 8) * 72))
                           + (lane & 3) * 8;
        float gs0 = 0.f, gs1 = 0.f;
#pragma unroll
        for (int i = 0; i < 8; i++) {
            float2 fk = h22f2(kg[i]);
            float2 f0 = h22f2(q0[i]);
            float2 f1 = h22f2(q1[i]);
            gs0 += f0.x * fk.x + f0.y * fk.y;
            gs1 += f1.x * fk.x + f1.y * fk.y;
        }
        gs0 += __shfl_xor_sync(0xffffffffu, gs0, 1);
        gs0 += __shfl_xor_sync(0xffffffffu, gs0, 2);
        gs1 += __shfl_xor_sync(0xffffffffu, gs1, 1);
        gs1 += __shfl_xor_sync(0xffffffffu, gs1, 2);

        float mn0 = fmaxf(m0, gs0), mn1 = fmaxf(m1, gs1);
        float s0 = __expf(m0 - mn0), s1 = __expf(m1 - mn1);
        float pg0 = __expf(gs0 - mn0), pg1 = __expf(gs1 - mn1);
        l0 = l0 * s0 + pg0;
        l1 = l1 * s1 + pg1;
        const uint32_t* vg = qkvh + (rowbase + SEQ - 1) * QKVW + 512 + h * 32
                           + (lane & 3);
#pragma unroll
        for (int nf = 0; nf < 8; nf++) {
            float2 fv = h22f2(vg[nf * 4]);
            od[nf][0] = od[nf][0] * s0 + pg0 * fv.x;
            od[nf][1] = od[nf][1] * s0 + pg0 * fv.y;
            od[nf][2] = od[nf][2] * s1 + pg1 * fv.x;
            od[nf][3] = od[nf][3] * s1 + pg1 * fv.y;
        }
    }

    const float inv0 = 1.0f / l0, inv1 = 1.0f / l1;
    const int t = t0 + r;
    float* o0 = out + ((size_t)b * SEQ + t) * DMODEL + h * DH + kl0;
    float* o1 = o0 + 8 * (size_t)DMODEL;
#pragma unroll
    for (int nf = 0; nf < 8; nf++) {
        *(float2*)(o0 + nf * 8) = make_float2(od[nf][0] * inv0, od[nf][1] * inv0);
        *(float2*)(o1 + nf * 8) = make_float2(od[nf][2] * inv1, od[nf][3] * inv1);
    }
}

// ---------------------------------------------------------------------------
// Residual + LayerNorm -> hn fp32 + packed fp16
// ---------------------------------------------------------------------------
__global__ __launch_bounds__(256)
void ln_kernel(const float* __restrict__ x, const float* __restrict__ attn,
               const float* __restrict__ gamma, const float* __restrict__ beta,
               float* __restrict__ hn, uint32_t* __restrict__ hnh)
{
    const int r = blockIdx.x;
    const int b = r / S0;
    const int s = r - b * S0;
    const int tid = threadIdx.x;
    const int c = tid * 2;

    float2 xv = *(const float2*)(x + (size_t)r * DMODEL + c);
    float2 av = *(const float2*)(attn + ((size_t)b * SEQ + s) * DMODEL + c);
    float h0 = xv.x + av.x;
    float h1 = xv.y + av.y;
    float sum = h0 + h1;
    float sq  = h0 * h0 + h1 * h1;
#pragma unroll
    for (int off = 16; off; off >>= 1) {
        sum += __shfl_xor_sync(0xffffffffu, sum, off);
        sq  += __shfl_xor_sync(0xffffffffu, sq,  off);
    }
    __shared__ float rs[8], rq[8];
    int w = tid >> 5, lane = tid & 31;
    if (lane == 0) { rs[w] = sum; rq[w] = sq; }
    __syncthreads();
    float ts = 0.f, tq = 0.f;
#pragma unroll
    for (int i = 0; i < 8; i++) { ts += rs[i]; tq += rq[i]; }
    float mu   = ts * (1.0f / DMODEL);
    float var  = tq * (1.0f / DMODEL) - mu * mu;
    float rstd = rsqrtf(var + 1e-5f);
    float v0 = (h0 - mu) * rstd * gamma[c]     + beta[c];
    float v1 = (h1 - mu) * rstd * gamma[c + 1] + beta[c + 1];
    size_t base = (size_t)r * DMODEL;
    *(float2*)(hn + base + c) = make_float2(v0, v1);
    hnh[(base >> 1) + tid] = f2h2(v0, v1);
}

// ---------------------------------------------------------------------------
extern "C" void kernel_launch(void* const* d_in, const int* in_sizes, int n_in,
                              void* d_out, int out_size)
{
    const float* x   = (const float*)d_in[0];
    const float* Wq  = (const float*)d_in[2];
    const float* bq  = (const float*)d_in[3];
    const float* Wk  = (const float*)d_in[4];
    const float* bk  = (const float*)d_in[5];
    const float* Wv  = (const float*)d_in[6];
    const float* bv  = (const float*)d_in[7];
    const float* lng = (const float*)d_in[14];
    const float* lnb = (const float*)d_in[15];
    const float* W1  = (const float*)d_in[16];
    const float* b1  = (const float*)d_in[17];
    const float* W2  = (const float*)d_in[18];
    const float* b2  = (const float*)d_in[19];

    uint32_t *pxh, *pWqkv, *pW1t, *pW2t, *phnh, *pacth, *pqkvh;
    float *pbqkv, *pattn, *phn;
    cudaGetSymbolAddress((void**)&pxh,    g_xh);
    cudaGetSymbolAddress((void**)&pWqkv,  g_Wqkv);
    cudaGetSymbolAddress((void**)&pW1t,   g_W1t);
    cudaGetSymbolAddress((void**)&pW2t,   g_W2t);
    cudaGetSymbolAddress((void**)&pbqkv,  g_bqkv);
    cudaGetSymbolAddress((void**)&pqkvh,  g_qkvh);
    cudaGetSymbolAddress((void**)&pattn,  g_attn);
    cudaGetSymbolAddress((void**)&phn,    g_hn);
    cudaGetSymbolAddress((void**)&phnh,   g_hnh);
    cudaGetSymbolAddress((void**)&pacth,  g_acth);

    cudaFuncSetAttribute(hgemm2<0>, cudaFuncAttributeMaxDynamicSharedMemorySize, GSMEM);
    cudaFuncSetAttribute(hgemm2<1>, cudaFuncAttributeMaxDynamicSharedMemorySize, GSMEM);
    cudaFuncSetAttribute(hgemm2<2>, cudaFuncAttributeMaxDynamicSharedMemorySize, GSMEM);
    cudaFuncSetAttribute(attn_mma,  cudaFuncAttributeMaxDynamicSharedMemorySize, ASMEM);

    dim3 blk(256);

    // 1: bias  2: x->fp16  3: QKV weight transpose
    prep_bias<<<(QKVN + 255) / 256, blk>>>(bq, bk, bv, pbqkv);
    prep_x<<<(int)(((size_t)MPAD * DMODEL / 2 + 255) / 256), blk>>>(x, pxh);
    prep_wqkv_t<<<dim3(8, 16, 3), blk>>>(Wq, Wk, Wv, pWqkv);

    // 4: fused QKV GEMM (ncu target slot)
    hgemm2<0><<<dim3(QKVN / 128, MPAD / 128), blk, GSMEM>>>(
        pxh, pWqkv, pbqkv, nullptr, nullptr, pqkvh, MPAD, QKVN, DMODEL);

    // 5: tensor-core attention
    attn_mma<<<dim3(SEQ / 64, NH, BATCH), dim3(128), ASMEM>>>(pqkvh, pattn);

    // 6: W1 transpose  7: residual + LN  8: W2 transpose
    prep_wt2<<<dim3(8, 64), blk>>>(W1, pW1t, DFF, 256);
    ln_kernel<<<MROWS, blk>>>(x, pattn, lng, lnb, phn, phnh);
    prep_wt2<<<dim3(32, 16), blk>>>(W2, pW2t, DMODEL, 1024);

    // 9: FFN up + gelu -> fp16
    hgemm2<1><<<dim3(DFF / 128, MPAD / 128), blk, GSMEM>>>(
        phnh, pW1t, b1, nullptr, nullptr, pacth, MROWS, DFF, DMODEL);

    // 10: FFN down + bias + residual -> out
    hgemm2<2><<<dim3(DMODEL / 128, MPAD / 128), blk, GSMEM>>>(
        pacth, pW2t, b2, phn, (float*)d_out, nullptr, MROWS, DMODEL, DFF);
}